// round 1
// baseline (speedup 1.0000x reference)
#include <cuda_runtime.h>
#include <cuda_bf16.h>
#include <math.h>
#include <float.h>

// Problem constants
#define BATCH 2
#define SEQ   2048
#define EMB   2048
#define HEADS 16
#define DHEAD 128
#define MTOT  (BATCH*SEQ)     // 4096 tokens
#define NQKV  (3*EMB)         // 6144
#define BHT   (BATCH*HEADS)   // 32

// Scratch (no cudaMalloc allowed -> __device__ globals)
__device__ float g_qkv[(size_t)MTOT * NQKV];          // [4096, 6144]
__device__ float g_q  [(size_t)BHT * SEQ * DHEAD];    // [32, 2048, 128] (rope'd)
__device__ float g_k  [(size_t)BHT * SEQ * DHEAD];
__device__ float g_v  [(size_t)BHT * SEQ * DHEAD];
__device__ float g_attn[(size_t)MTOT * EMB];          // [4096, 2048]

// ---------------------------------------------------------------------------
// SGEMM: C[M,N] = A[M,K] @ B[K,N] + bias[N]   (all row-major, fp32)
// 128x128 block tile, BK=16, 8x8 per thread, 256 threads.
// All dims are multiples of tile sizes for this problem -> no bounds checks.
// ---------------------------------------------------------------------------
__global__ __launch_bounds__(256)
void sgemm_bias_kernel(int M, int N, int K,
                       const float* __restrict__ A,
                       const float* __restrict__ B,
                       const float* __restrict__ bias,
                       float* __restrict__ C)
{
    __shared__ __align__(16) float As[16][128];   // As[k][m]
    __shared__ __align__(16) float Bs[16][128];   // Bs[k][n]

    const int tid = threadIdx.x;
    const int tx  = tid & 15;       // n-tile group
    const int ty  = tid >> 4;       // m-tile group
    const int m0  = blockIdx.y * 128;
    const int n0  = blockIdx.x * 128;

    float acc[8][8];
#pragma unroll
    for (int i = 0; i < 8; i++)
#pragma unroll
        for (int j = 0; j < 8; j++) acc[i][j] = 0.f;

    const float* Ab = A + (size_t)m0 * K;
    const float* Bb = B + n0;

    for (int k0 = 0; k0 < K; k0 += 16) {
        // Load A tile 128x16 (transposed into As[k][m])
#pragma unroll
        for (int i = 0; i < 2; i++) {
            int f = tid + i * 256;            // 512 float4
            int r = f >> 2;                   // 0..127
            int c = (f & 3) << 2;             // 0,4,8,12
            float4 v = *reinterpret_cast<const float4*>(Ab + (size_t)r * K + k0 + c);
            As[c + 0][r] = v.x; As[c + 1][r] = v.y;
            As[c + 2][r] = v.z; As[c + 3][r] = v.w;
        }
        // Load B tile 16x128
#pragma unroll
        for (int i = 0; i < 2; i++) {
            int f = tid + i * 256;
            int r = f >> 5;                   // 0..15
            int c = (f & 31) << 2;            // 0..124
            *reinterpret_cast<float4*>(&Bs[r][c]) =
                *reinterpret_cast<const float4*>(Bb + (size_t)(k0 + r) * N + c);
        }
        __syncthreads();

#pragma unroll
        for (int k = 0; k < 16; k++) {
            float a[8], b[8];
            *reinterpret_cast<float4*>(a)     = *reinterpret_cast<const float4*>(&As[k][ty * 8]);
            *reinterpret_cast<float4*>(a + 4) = *reinterpret_cast<const float4*>(&As[k][ty * 8 + 4]);
            *reinterpret_cast<float4*>(b)     = *reinterpret_cast<const float4*>(&Bs[k][tx * 8]);
            *reinterpret_cast<float4*>(b + 4) = *reinterpret_cast<const float4*>(&Bs[k][tx * 8 + 4]);
#pragma unroll
            for (int i = 0; i < 8; i++)
#pragma unroll
                for (int j = 0; j < 8; j++)
                    acc[i][j] = fmaf(a[i], b[j], acc[i][j]);
        }
        __syncthreads();
    }

#pragma unroll
    for (int i = 0; i < 8; i++) {
        int gm = m0 + ty * 8 + i;
        float* Crow = C + (size_t)gm * N + n0 + tx * 8;
        const float* brow = bias + n0 + tx * 8;
        float4 o0, o1;
        o0.x = acc[i][0] + brow[0];
        o0.y = acc[i][1] + brow[1];
        o0.z = acc[i][2] + brow[2];
        o0.w = acc[i][3] + brow[3];
        o1.x = acc[i][4] + brow[4];
        o1.y = acc[i][5] + brow[5];
        o1.z = acc[i][6] + brow[6];
        o1.w = acc[i][7] + brow[7];
        *reinterpret_cast<float4*>(Crow)     = o0;
        *reinterpret_cast<float4*>(Crow + 4) = o1;
    }
}

// ---------------------------------------------------------------------------
// RoPE + split + head transpose.
// qkv: [4096, 6144]  ->  Q,K (rope'd), V in [B*H, N, 128]
// One thread per (token, head, j<64) handles the rotation pair (j, j+64).
//
// CRITICAL: reference computes theta in bf16:
//   theta = fp32( bf16( 1 / bf16( 10000 ** (j/64) ) ) )
// We replicate both bf16 roundings exactly (pow in double -> exact RN).
// ---------------------------------------------------------------------------
__global__ __launch_bounds__(256)
void rope_split_kernel(const float* __restrict__ qkv,
                       float* __restrict__ Q,
                       float* __restrict__ K,
                       float* __restrict__ V)
{
    int idx = blockIdx.x * 256 + threadIdx.x;     // MTOT*HEADS*64 total
    if (idx >= MTOT * HEADS * 64) return;
    int j = idx & 63;
    int h = (idx >> 6) & (HEADS - 1);
    int t = idx >> 10;                            // token 0..4095
    int n = t & (SEQ - 1);
    int b = t >> 11;

    const float* base = qkv + (size_t)t * NQKV + h * DHEAD;
    float q1 = base[j],           q2 = base[j + 64];
    float k1 = base[EMB + j],     k2 = base[EMB + j + 64];
    float v1 = base[2 * EMB + j], v2 = base[2 * EMB + j + 64];

    float pf = __bfloat162float(__float2bfloat16(
                   (float)pow(10000.0, (double)j * (1.0 / 64.0))));
    float th = __bfloat162float(__float2bfloat16(1.0f / pf));
    float fr = (float)n * th;
    float sn, cs;
    sincosf(fr, &sn, &cs);

    size_t o = ((size_t)(b * HEADS + h) * SEQ + n) * DHEAD + j;
    Q[o]      = q1 * cs - q2 * sn;
    Q[o + 64] = q1 * sn + q2 * cs;
    K[o]      = k1 * cs - k2 * sn;
    K[o + 64] = k1 * sn + k2 * cs;
    V[o]      = v1;
    V[o + 64] = v2;
}

// ---------------------------------------------------------------------------
// Causal flash attention, fp32. BM=BN=64, d=128, 256 threads.
// Grid: (N/64 q-blocks, B*H). Output written in [B, N, H*128] token-major
// layout so the output projection GEMM can consume it directly.
// ---------------------------------------------------------------------------
__global__ __launch_bounds__(256)
void flash_attn_kernel(const float* __restrict__ Q,
                       const float* __restrict__ K,
                       const float* __restrict__ V,
                       float* __restrict__ O)
{
    extern __shared__ __align__(16) float sm[];
    float* Qs  = sm;                 // [64][128]
    float* KsT = Qs + 64 * 128;      // [128][64]  (K transposed: [d][k])
    float* Vs  = KsT + 128 * 64;     // [64][128]
    float* Ps  = Vs + 64 * 128;      // [64][64]

    const int tid = threadIdx.x;
    const int tx  = tid & 15;
    const int ty  = tid >> 4;
    const int qb  = blockIdx.x;
    const int bh  = blockIdx.y;
    const float scale = 0.08838834764831845f;    // 1/sqrt(128)

    // Load Q tile (flat copy, fully coalesced)
    const float* Qg = Q + ((size_t)bh * SEQ + qb * 64) * DHEAD;
#pragma unroll
    for (int i = 0; i < 8; i++) {
        int f = tid + i * 256;
        reinterpret_cast<float4*>(Qs)[f] = reinterpret_cast<const float4*>(Qg)[f];
    }

    float o[4][8];
    float m[4], l[4];
#pragma unroll
    for (int i = 0; i < 4; i++) {
        m[i] = -FLT_MAX; l[i] = 0.f;
#pragma unroll
        for (int j = 0; j < 8; j++) o[i][j] = 0.f;
    }

    for (int kb = 0; kb <= qb; ++kb) {
        const float* Kg = K + ((size_t)bh * SEQ + kb * 64) * DHEAD;
        const float* Vg = V + ((size_t)bh * SEQ + kb * 64) * DHEAD;

        __syncthreads();   // previous tile fully consumed (also covers Q stores on kb=0)

        // K tile transposed into KsT[d][k]. Mapping keeps STS conflict-free:
        // consecutive lanes write consecutive k for a fixed d.
#pragma unroll
        for (int i = 0; i < 8; i++) {
            int f  = tid + i * 256;          // 0..2047 float4 ids
            int r  = f & 63;                 // k row
            int c4 = f >> 6;                 // d group (0..31)
            float4 v = reinterpret_cast<const float4*>(Kg)[r * 32 + c4];
            int c = c4 << 2;
            KsT[(c + 0) * 64 + r] = v.x;
            KsT[(c + 1) * 64 + r] = v.y;
            KsT[(c + 2) * 64 + r] = v.z;
            KsT[(c + 3) * 64 + r] = v.w;
            // V flat copy (coalesced)
            reinterpret_cast<float4*>(Vs)[f] = reinterpret_cast<const float4*>(Vg)[f];
        }
        __syncthreads();

        // S = Q @ K^T : each thread owns 4 q-rows x 4 k-cols
        float s[4][4];
#pragma unroll
        for (int i = 0; i < 4; i++)
#pragma unroll
            for (int j = 0; j < 4; j++) s[i][j] = 0.f;

#pragma unroll 4
        for (int d0 = 0; d0 < DHEAD; d0 += 4) {
            float qr[4][4];
#pragma unroll
            for (int i = 0; i < 4; i++) {
                float4 t4 = *reinterpret_cast<const float4*>(&Qs[(ty * 4 + i) * DHEAD + d0]);
                qr[i][0] = t4.x; qr[i][1] = t4.y; qr[i][2] = t4.z; qr[i][3] = t4.w;
            }
#pragma unroll
            for (int u = 0; u < 4; u++) {
                float4 kv = *reinterpret_cast<const float4*>(&KsT[(d0 + u) * 64 + tx * 4]);
#pragma unroll
                for (int i = 0; i < 4; i++) {
                    s[i][0] = fmaf(qr[i][u], kv.x, s[i][0]);
                    s[i][1] = fmaf(qr[i][u], kv.y, s[i][1]);
                    s[i][2] = fmaf(qr[i][u], kv.z, s[i][2]);
                    s[i][3] = fmaf(qr[i][u], kv.w, s[i][3]);
                }
            }
        }

        // scale + causal mask + online softmax update
        const bool diag  = (kb == qb);
        const int qrow0 = qb * 64 + ty * 4;
        const int kcol0 = kb * 64 + tx * 4;
#pragma unroll
        for (int i = 0; i < 4; i++) {
#pragma unroll
            for (int j = 0; j < 4; j++) {
                s[i][j] *= scale;
                if (diag && (kcol0 + j > qrow0 + i)) s[i][j] = -FLT_MAX;
            }
            float mx = fmaxf(fmaxf(s[i][0], s[i][1]), fmaxf(s[i][2], s[i][3]));
#pragma unroll
            for (int off = 8; off > 0; off >>= 1)
                mx = fmaxf(mx, __shfl_xor_sync(0xffffffffu, mx, off));
            float mn    = fmaxf(m[i], mx);
            float alpha = expf(m[i] - mn);
            float p[4], rs = 0.f;
#pragma unroll
            for (int j = 0; j < 4; j++) { p[j] = expf(s[i][j] - mn); rs += p[j]; }
#pragma unroll
            for (int off = 8; off > 0; off >>= 1)
                rs += __shfl_xor_sync(0xffffffffu, rs, off);
            l[i] = l[i] * alpha + rs;
            m[i] = mn;
#pragma unroll
            for (int j = 0; j < 8; j++) o[i][j] *= alpha;
            *reinterpret_cast<float4*>(&Ps[(ty * 4 + i) * 64 + tx * 4]) =
                make_float4(p[0], p[1], p[2], p[3]);
        }
        __syncthreads();

        // O += P @ V : thread owns 4 rows x 8 d-cols
#pragma unroll 2
        for (int k2 = 0; k2 < 64; k2++) {
            float4 va = *reinterpret_cast<const float4*>(&Vs[k2 * DHEAD + tx * 8]);
            float4 vb = *reinterpret_cast<const float4*>(&Vs[k2 * DHEAD + tx * 8 + 4]);
#pragma unroll
            for (int i = 0; i < 4; i++) {
                float p = Ps[(ty * 4 + i) * 64 + k2];
                o[i][0] = fmaf(p, va.x, o[i][0]);
                o[i][1] = fmaf(p, va.y, o[i][1]);
                o[i][2] = fmaf(p, va.z, o[i][2]);
                o[i][3] = fmaf(p, va.w, o[i][3]);
                o[i][4] = fmaf(p, vb.x, o[i][4]);
                o[i][5] = fmaf(p, vb.y, o[i][5]);
                o[i][6] = fmaf(p, vb.z, o[i][6]);
                o[i][7] = fmaf(p, vb.w, o[i][7]);
            }
        }
    }

    // normalize + write out in [B, N, H*128] token-major layout
    const int b = bh >> 4, h = bh & 15;
#pragma unroll
    for (int i = 0; i < 4; i++) {
        float inv = 1.0f / l[i];
        int n = qb * 64 + ty * 4 + i;
        float* dst = O + ((size_t)(b * SEQ + n)) * EMB + h * DHEAD + tx * 8;
        *reinterpret_cast<float4*>(dst) =
            make_float4(o[i][0] * inv, o[i][1] * inv, o[i][2] * inv, o[i][3] * inv);
        *reinterpret_cast<float4*>(dst + 4) =
            make_float4(o[i][4] * inv, o[i][5] * inv, o[i][6] * inv, o[i][7] * inv);
    }
}

// ---------------------------------------------------------------------------
// Launch
// ---------------------------------------------------------------------------
extern "C" void kernel_launch(void* const* d_in, const int* in_sizes, int n_in,
                              void* d_out, int out_size)
{
    const float* x    = (const float*)d_in[0];   // [2,2048,2048]
    const float* Wqkv = (const float*)d_in[1];   // [2048,6144]
    const float* bqkv = (const float*)d_in[2];   // [6144]
    const float* Wo   = (const float*)d_in[3];   // [2048,2048]
    const float* bo   = (const float*)d_in[4];   // [2048]
    float* out = (float*)d_out;                  // [2,2048,2048]
    (void)in_sizes; (void)n_in; (void)out_size;

    float *qkv, *q, *k, *v, *attn;
    cudaGetSymbolAddress((void**)&qkv,  g_qkv);
    cudaGetSymbolAddress((void**)&q,    g_q);
    cudaGetSymbolAddress((void**)&k,    g_k);
    cudaGetSymbolAddress((void**)&v,    g_v);
    cudaGetSymbolAddress((void**)&attn, g_attn);

    const int fa_smem = (64 * 128 + 128 * 64 + 64 * 128 + 64 * 64) * (int)sizeof(float);
    cudaFuncSetAttribute(flash_attn_kernel,
                         cudaFuncAttributeMaxDynamicSharedMemorySize, fa_smem);

    // 1) QKV projection
    dim3 g1(NQKV / 128, MTOT / 128);
    sgemm_bias_kernel<<<g1, 256>>>(MTOT, NQKV, EMB, x, Wqkv, bqkv, qkv);

    // 2) RoPE + split + head transpose
    rope_split_kernel<<<(MTOT * HEADS * 64) / 256, 256>>>(qkv, q, k, v);

    // 3) Causal flash attention
    flash_attn_kernel<<<dim3(SEQ / 64, BHT), 256, fa_smem>>>(q, k, v, attn);

    // 4) Output projection
    dim3 g2(EMB / 128, MTOT / 128);
    sgemm_bias_kernel<<<g2, 256>>>(MTOT, EMB, EMB, attn, Wo, bo, out);
}

// round 4
// speedup vs baseline: 1.7803x; 1.7803x over previous
#include <cuda_runtime.h>
#include <cuda_bf16.h>
#include <math.h>
#include <float.h>
#include <stdint.h>

// ---------------------------------------------------------------------------
// Problem constants
// ---------------------------------------------------------------------------
#define BATCH 2
#define SEQ   2048
#define EMB   2048
#define HEADS 16
#define DHEAD 128
#define MTOT  (BATCH*SEQ)     // 4096
#define NQKV  (3*EMB)         // 6144
#define BHT   (BATCH*HEADS)   // 32
#define KDIM  2048

// ---------------------------------------------------------------------------
// Global scratch (no cudaMalloc allowed)
// ---------------------------------------------------------------------------
__device__ float g_qkv [(size_t)MTOT * NQKV];
__device__ float g_q   [(size_t)BHT * SEQ * DHEAD];
__device__ float g_k   [(size_t)BHT * SEQ * DHEAD];
__device__ float g_v   [(size_t)BHT * SEQ * DHEAD];
__device__ float g_attn[(size_t)MTOT * EMB];

__device__ __nv_bfloat16 g_xhi[(size_t)MTOT * EMB];
__device__ __nv_bfloat16 g_xlo[(size_t)MTOT * EMB];
__device__ __nv_bfloat16 g_ahi[(size_t)MTOT * EMB];
__device__ __nv_bfloat16 g_alo[(size_t)MTOT * EMB];
__device__ __nv_bfloat16 g_wqhi[(size_t)NQKV * KDIM];   // W_qkv^T hi  [6144][2048]
__device__ __nv_bfloat16 g_wqlo[(size_t)NQKV * KDIM];
__device__ __nv_bfloat16 g_wohi[(size_t)EMB * KDIM];    // W_o^T hi    [2048][2048]
__device__ __nv_bfloat16 g_wolo[(size_t)EMB * KDIM];

// ---------------------------------------------------------------------------
// PTX helpers (sm_100 BASELINE only: mma.sync / ldmatrix / cp.async)
// ---------------------------------------------------------------------------
__device__ __forceinline__ uint32_t smem_u32(const void* p) {
    uint32_t a;
    asm("{ .reg .u64 t; cvta.to.shared.u64 t, %1; cvt.u32.u64 %0, t; }" : "=r"(a) : "l"(p));
    return a;
}

__device__ __forceinline__ void cp16(uint32_t s, const void* g) {
    asm volatile("cp.async.cg.shared.global [%0], [%1], 16;" :: "r"(s), "l"(g));
}
#define CP_COMMIT() asm volatile("cp.async.commit_group;" ::: "memory")
#define CP_WAIT(N)  asm volatile("cp.async.wait_group %0;" :: "n"(N) : "memory")

__device__ __forceinline__ void ldsm_x4(uint32_t r[4], uint32_t addr) {
    asm volatile("ldmatrix.sync.aligned.m8n8.x4.shared.b16 {%0,%1,%2,%3}, [%4];"
                 : "=r"(r[0]), "=r"(r[1]), "=r"(r[2]), "=r"(r[3]) : "r"(addr));
}

__device__ __forceinline__ void mma_bf16(float c[4], const uint32_t a[4],
                                         uint32_t b0, uint32_t b1) {
    asm volatile("mma.sync.aligned.m16n8k16.row.col.f32.bf16.bf16.f32 "
                 "{%0,%1,%2,%3}, {%4,%5,%6,%7}, {%8,%9}, {%0,%1,%2,%3};"
                 : "+f"(c[0]), "+f"(c[1]), "+f"(c[2]), "+f"(c[3])
                 : "r"(a[0]), "r"(a[1]), "r"(a[2]), "r"(a[3]), "r"(b0), "r"(b1));
}

// ---------------------------------------------------------------------------
// Split-bf16 GEMM via mma.sync:  C[M,Nt] = A[M,2048] @ B^T + bias
// A: hi/lo bf16 row-major [M][2048]; B: hi/lo bf16 [Nt][2048] (K-major).
// 3 passes (AhBh + AlBh + AhBl) fused per k-step for fp32-like precision.
// Block 128x128, BK=64, 8 warps (warp tile 32x64), cp.async double buffer.
// SMEM row = 64 bf16 = 128B = 8 x 16B units; unit swizzled by (u ^ (row&7)).
// ---------------------------------------------------------------------------
#define GBK 64
#define NCHUNK (KDIM / GBK)              // 32
#define MAT_BYTES 16384                   // 128 x 64 bf16
#define STAGE_BYTES (4 * MAT_BYTES)       // Ah, Al, Bh, Bl
#define GEMM_SMEM (2 * STAGE_BYTES)       // 131072

__device__ __forceinline__ void load_stage(uint32_t st,
    const __nv_bfloat16* __restrict__ Ah, const __nv_bfloat16* __restrict__ Al,
    const __nv_bfloat16* __restrict__ Bh, const __nv_bfloat16* __restrict__ Bl,
    int k0, int tid)
{
#pragma unroll
    for (int i = 0; i < 16; i++) {
        int c   = tid + (i << 8);          // 0..4095
        int row = (c & 1023) >> 3;         // 0..127
        int u   = c & 7;                   // 16B unit in row
        size_t   goff = (size_t)row * KDIM + k0 + u * 8;
        uint32_t soff = row * 128 + ((u ^ (row & 7)) << 4);
        const __nv_bfloat16* g; uint32_t mb;
        switch (i >> 2) {
            case 0:  g = Ah; mb = 0;             break;
            case 1:  g = Al; mb = MAT_BYTES;     break;
            case 2:  g = Bh; mb = 2 * MAT_BYTES; break;
            default: g = Bl; mb = 3 * MAT_BYTES; break;
        }
        cp16(st + mb + soff, g + goff);
    }
}

__device__ __forceinline__ void compute_chunk(uint32_t st, int lane, int wm, int wn,
                                              float acc[2][8][4])
{
    const int aRow0 = wm * 32 + ((lane >> 3) & 1) * 8 + (lane & 7);
    const int bRow0 = wn * 64 + ((lane >> 4) << 3) + (lane & 7);
    const int au = (lane >> 4);        // A: unit select by lane 16-31
    const int bu = ((lane >> 3) & 1);  // B: unit select by lane 8-15/24-31
#pragma unroll
    for (int ks = 0; ks < 4; ks++) {
        uint32_t ah[2][4], al[2][4];
#pragma unroll
        for (int mt = 0; mt < 2; mt++) {
            int row = aRow0 + mt * 16;
            int u   = ks * 2 + au;
            uint32_t off = row * 128 + ((u ^ (row & 7)) << 4);
            ldsm_x4(ah[mt], st + off);
            ldsm_x4(al[mt], st + MAT_BYTES + off);
        }
        uint32_t bh[4][4], bl[4][4];
#pragma unroll
        for (int ng = 0; ng < 4; ng++) {
            int row = bRow0 + ng * 16;
            int u   = ks * 2 + bu;
            uint32_t off = row * 128 + ((u ^ (row & 7)) << 4);
            ldsm_x4(bh[ng], st + 2 * MAT_BYTES + off);
            ldsm_x4(bl[ng], st + 3 * MAT_BYTES + off);
        }
#pragma unroll
        for (int mt = 0; mt < 2; mt++)
#pragma unroll
            for (int ng = 0; ng < 4; ng++) {
                mma_bf16(acc[mt][ng * 2],     ah[mt], bh[ng][0], bh[ng][1]);
                mma_bf16(acc[mt][ng * 2],     al[mt], bh[ng][0], bh[ng][1]);
                mma_bf16(acc[mt][ng * 2],     ah[mt], bl[ng][0], bl[ng][1]);
                mma_bf16(acc[mt][ng * 2 + 1], ah[mt], bh[ng][2], bh[ng][3]);
                mma_bf16(acc[mt][ng * 2 + 1], al[mt], bh[ng][2], bh[ng][3]);
                mma_bf16(acc[mt][ng * 2 + 1], ah[mt], bl[ng][2], bl[ng][3]);
            }
    }
}

__global__ __launch_bounds__(256)
void gemm_mma_kernel(const __nv_bfloat16* __restrict__ Ahi, const __nv_bfloat16* __restrict__ Alo,
                     const __nv_bfloat16* __restrict__ Bhi, const __nv_bfloat16* __restrict__ Blo,
                     const float* __restrict__ bias, float* __restrict__ C, int Nt)
{
    extern __shared__ __align__(1024) char sm[];
    const uint32_t sbase = smem_u32(sm);
    const int tid  = threadIdx.x;
    const int lane = tid & 31;
    const int wid  = tid >> 5;
    const int wm   = wid & 3;       // 4 warps along M (32 rows each)
    const int wn   = wid >> 2;      // 2 warps along N (64 cols each)
    const int m0 = blockIdx.y * 128;
    const int n0 = blockIdx.x * 128;

    const __nv_bfloat16* Ahb = Ahi + (size_t)m0 * KDIM;
    const __nv_bfloat16* Alb = Alo + (size_t)m0 * KDIM;
    const __nv_bfloat16* Bhb = Bhi + (size_t)n0 * KDIM;
    const __nv_bfloat16* Blb = Blo + (size_t)n0 * KDIM;

    float acc[2][8][4];
#pragma unroll
    for (int a = 0; a < 2; a++)
#pragma unroll
        for (int b = 0; b < 8; b++)
#pragma unroll
            for (int c = 0; c < 4; c++) acc[a][b][c] = 0.f;

    load_stage(sbase, Ahb, Alb, Bhb, Blb, 0, tid);
    CP_COMMIT();

    for (int c = 0; c < NCHUNK; c++) {
        if (c + 1 < NCHUNK) {
            load_stage(sbase + ((c + 1) & 1) * STAGE_BYTES,
                       Ahb, Alb, Bhb, Blb, (c + 1) * GBK, tid);
            CP_COMMIT();
            CP_WAIT(1);
        } else {
            CP_WAIT(0);
        }
        __syncthreads();
        compute_chunk(sbase + (c & 1) * STAGE_BYTES, lane, wm, wn, acc);
        __syncthreads();
    }

    // Epilogue: fragment owner writes directly to global with bias.
    const int g   = lane >> 2;
    const int tg2 = (lane & 3) * 2;
#pragma unroll
    for (int mt = 0; mt < 2; mt++) {
        int r0 = m0 + wm * 32 + mt * 16 + g;
#pragma unroll
        for (int ng = 0; ng < 8; ng++) {
            int col = n0 + wn * 64 + ng * 8 + tg2;
            float b0 = bias[col], b1 = bias[col + 1];
            float2 v0 = make_float2(acc[mt][ng][0] + b0, acc[mt][ng][1] + b1);
            float2 v1 = make_float2(acc[mt][ng][2] + b0, acc[mt][ng][3] + b1);
            *(float2*)&C[(size_t)r0 * Nt + col]       = v0;
            *(float2*)&C[(size_t)(r0 + 8) * Nt + col] = v1;
        }
    }
}

// ---------------------------------------------------------------------------
// Prep: transpose + split weights  W[K][Nt] fp32 -> Wt_hi/lo[Nt][K] bf16
// ---------------------------------------------------------------------------
__global__ void wtrans_kernel(const float* __restrict__ W,
                              __nv_bfloat16* __restrict__ Whi,
                              __nv_bfloat16* __restrict__ Wlo, int Nt)
{
    __shared__ float t[32][33];
    const int tx = threadIdx.x, ty = threadIdx.y;
    const int n0 = blockIdx.x * 32, k0 = blockIdx.y * 32;
#pragma unroll
    for (int i = 0; i < 32; i += 8)
        t[ty + i][tx] = W[(size_t)(k0 + ty + i) * Nt + n0 + tx];
    __syncthreads();
#pragma unroll
    for (int i = 0; i < 32; i += 8) {
        float v = t[tx][ty + i];
        __nv_bfloat16 h = __float2bfloat16(v);
        __nv_bfloat16 l = __float2bfloat16(v - __bfloat162float(h));
        size_t o = (size_t)(n0 + ty + i) * KDIM + k0 + tx;
        Whi[o] = h; Wlo[o] = l;
    }
}

// ---------------------------------------------------------------------------
// Prep: elementwise split  X fp32 -> hi/lo bf16
// ---------------------------------------------------------------------------
__global__ __launch_bounds__(256)
void cvt_hilo_kernel(const float* __restrict__ X,
                     __nv_bfloat16* __restrict__ Hi, __nv_bfloat16* __restrict__ Lo, int n4)
{
    int i = blockIdx.x * 256 + threadIdx.x;
    if (i >= n4) return;
    float4 v = ((const float4*)X)[i];
    union { __nv_bfloat16 b[4]; uint2 u; } hh, ll;
    float f[4] = {v.x, v.y, v.z, v.w};
#pragma unroll
    for (int j = 0; j < 4; j++) {
        hh.b[j] = __float2bfloat16(f[j]);
        ll.b[j] = __float2bfloat16(f[j] - __bfloat162float(hh.b[j]));
    }
    ((uint2*)Hi)[i] = hh.u;
    ((uint2*)Lo)[i] = ll.u;
}

// ---------------------------------------------------------------------------
// RoPE + split + head transpose (bf16 theta replication — matches reference)
// ---------------------------------------------------------------------------
__global__ __launch_bounds__(256)
void rope_split_kernel(const float* __restrict__ qkv,
                       float* __restrict__ Q, float* __restrict__ K, float* __restrict__ V)
{
    int idx = blockIdx.x * 256 + threadIdx.x;
    if (idx >= MTOT * HEADS * 64) return;
    int j = idx & 63;
    int h = (idx >> 6) & (HEADS - 1);
    int t = idx >> 10;
    int n = t & (SEQ - 1);
    int b = t >> 11;

    const float* base = qkv + (size_t)t * NQKV + h * DHEAD;
    float q1 = base[j],           q2 = base[j + 64];
    float k1 = base[EMB + j],     k2 = base[EMB + j + 64];
    float v1 = base[2 * EMB + j], v2 = base[2 * EMB + j + 64];

    float pf = __bfloat162float(__float2bfloat16(
                   (float)pow(10000.0, (double)j * (1.0 / 64.0))));
    float th = __bfloat162float(__float2bfloat16(1.0f / pf));
    float fr = (float)n * th;
    float sn, cs;
    sincosf(fr, &sn, &cs);

    size_t o = ((size_t)(b * HEADS + h) * SEQ + n) * DHEAD + j;
    Q[o]      = q1 * cs - q2 * sn;
    Q[o + 64] = q1 * sn + q2 * cs;
    K[o]      = k1 * cs - k2 * sn;
    K[o + 64] = k1 * sn + k2 * cs;
    V[o]      = v1;
    V[o + 64] = v2;
}

// ---------------------------------------------------------------------------
// Causal flash attention, fp32 (unchanged; tensor-ize next round)
// ---------------------------------------------------------------------------
__global__ __launch_bounds__(256)
void flash_attn_kernel(const float* __restrict__ Q, const float* __restrict__ K,
                       const float* __restrict__ V, float* __restrict__ O)
{
    extern __shared__ __align__(16) float smf[];
    float* Qs  = smf;
    float* KsT = Qs + 64 * 128;
    float* Vs  = KsT + 128 * 64;
    float* Ps  = Vs + 64 * 128;

    const int tid = threadIdx.x;
    const int tx  = tid & 15;
    const int ty  = tid >> 4;
    const int qb  = blockIdx.x;
    const int bh  = blockIdx.y;
    const float scale = 0.08838834764831845f;

    const float* Qg = Q + ((size_t)bh * SEQ + qb * 64) * DHEAD;
#pragma unroll
    for (int i = 0; i < 8; i++) {
        int f = tid + i * 256;
        reinterpret_cast<float4*>(Qs)[f] = reinterpret_cast<const float4*>(Qg)[f];
    }

    float o[4][8];
    float m[4], l[4];
#pragma unroll
    for (int i = 0; i < 4; i++) {
        m[i] = -FLT_MAX; l[i] = 0.f;
#pragma unroll
        for (int j = 0; j < 8; j++) o[i][j] = 0.f;
    }

    for (int kb = 0; kb <= qb; ++kb) {
        const float* Kg = K + ((size_t)bh * SEQ + kb * 64) * DHEAD;
        const float* Vg = V + ((size_t)bh * SEQ + kb * 64) * DHEAD;

        __syncthreads();
#pragma unroll
        for (int i = 0; i < 8; i++) {
            int f  = tid + i * 256;
            int r  = f & 63;
            int c4 = f >> 6;
            float4 v = reinterpret_cast<const float4*>(Kg)[r * 32 + c4];
            int c = c4 << 2;
            KsT[(c + 0) * 64 + r] = v.x;
            KsT[(c + 1) * 64 + r] = v.y;
            KsT[(c + 2) * 64 + r] = v.z;
            KsT[(c + 3) * 64 + r] = v.w;
            reinterpret_cast<float4*>(Vs)[f] = reinterpret_cast<const float4*>(Vg)[f];
        }
        __syncthreads();

        float s[4][4];
#pragma unroll
        for (int i = 0; i < 4; i++)
#pragma unroll
            for (int j = 0; j < 4; j++) s[i][j] = 0.f;

#pragma unroll 4
        for (int d0 = 0; d0 < DHEAD; d0 += 4) {
            float qr[4][4];
#pragma unroll
            for (int i = 0; i < 4; i++) {
                float4 t4 = *reinterpret_cast<const float4*>(&Qs[(ty * 4 + i) * DHEAD + d0]);
                qr[i][0] = t4.x; qr[i][1] = t4.y; qr[i][2] = t4.z; qr[i][3] = t4.w;
            }
#pragma unroll
            for (int u = 0; u < 4; u++) {
                float4 kv = *reinterpret_cast<const float4*>(&KsT[(d0 + u) * 64 + tx * 4]);
#pragma unroll
                for (int i = 0; i < 4; i++) {
                    s[i][0] = fmaf(qr[i][u], kv.x, s[i][0]);
                    s[i][1] = fmaf(qr[i][u], kv.y, s[i][1]);
                    s[i][2] = fmaf(qr[i][u], kv.z, s[i][2]);
                    s[i][3] = fmaf(qr[i][u], kv.w, s[i][3]);
                }
            }
        }

        const bool diag  = (kb == qb);
        const int qrow0 = qb * 64 + ty * 4;
        const int kcol0 = kb * 64 + tx * 4;
#pragma unroll
        for (int i = 0; i < 4; i++) {
#pragma unroll
            for (int j = 0; j < 4; j++) {
                s[i][j] *= scale;
                if (diag && (kcol0 + j > qrow0 + i)) s[i][j] = -FLT_MAX;
            }
            float mx = fmaxf(fmaxf(s[i][0], s[i][1]), fmaxf(s[i][2], s[i][3]));
#pragma unroll
            for (int off = 8; off > 0; off >>= 1)
                mx = fmaxf(mx, __shfl_xor_sync(0xffffffffu, mx, off));
            float mn    = fmaxf(m[i], mx);
            float alpha = expf(m[i] - mn);
            float p[4], rs = 0.f;
#pragma unroll
            for (int j = 0; j < 4; j++) { p[j] = expf(s[i][j] - mn); rs += p[j]; }
#pragma unroll
            for (int off = 8; off > 0; off >>= 1)
                rs += __shfl_xor_sync(0xffffffffu, rs, off);
            l[i] = l[i] * alpha + rs;
            m[i] = mn;
#pragma unroll
            for (int j = 0; j < 8; j++) o[i][j] *= alpha;
            *reinterpret_cast<float4*>(&Ps[(ty * 4 + i) * 64 + tx * 4]) =
                make_float4(p[0], p[1], p[2], p[3]);
        }
        __syncthreads();

#pragma unroll 2
        for (int k2 = 0; k2 < 64; k2++) {
            float4 va = *reinterpret_cast<const float4*>(&Vs[k2 * DHEAD + tx * 8]);
            float4 vb = *reinterpret_cast<const float4*>(&Vs[k2 * DHEAD + tx * 8 + 4]);
#pragma unroll
            for (int i = 0; i < 4; i++) {
                float p = Ps[(ty * 4 + i) * 64 + k2];
                o[i][0] = fmaf(p, va.x, o[i][0]);
                o[i][1] = fmaf(p, va.y, o[i][1]);
                o[i][2] = fmaf(p, va.z, o[i][2]);
                o[i][3] = fmaf(p, va.w, o[i][3]);
                o[i][4] = fmaf(p, vb.x, o[i][4]);
                o[i][5] = fmaf(p, vb.y, o[i][5]);
                o[i][6] = fmaf(p, vb.z, o[i][6]);
                o[i][7] = fmaf(p, vb.w, o[i][7]);
            }
        }
    }

    const int b = bh >> 4, h = bh & 15;
#pragma unroll
    for (int i = 0; i < 4; i++) {
        float inv = 1.0f / l[i];
        int n = qb * 64 + ty * 4 + i;
        float* dst = O + ((size_t)(b * SEQ + n)) * EMB + h * DHEAD + tx * 8;
        *reinterpret_cast<float4*>(dst) =
            make_float4(o[i][0] * inv, o[i][1] * inv, o[i][2] * inv, o[i][3] * inv);
        *reinterpret_cast<float4*>(dst + 4) =
            make_float4(o[i][4] * inv, o[i][5] * inv, o[i][6] * inv, o[i][7] * inv);
    }
}

// ---------------------------------------------------------------------------
// Launch
// ---------------------------------------------------------------------------
extern "C" void kernel_launch(void* const* d_in, const int* in_sizes, int n_in,
                              void* d_out, int out_size)
{
    const float* x    = (const float*)d_in[0];
    const float* Wqkv = (const float*)d_in[1];
    const float* bqkv = (const float*)d_in[2];
    const float* Wo   = (const float*)d_in[3];
    const float* bo   = (const float*)d_in[4];
    float* out = (float*)d_out;
    (void)in_sizes; (void)n_in; (void)out_size;

    float *qkv, *q, *k, *v, *attn;
    __nv_bfloat16 *xhi, *xlo, *ahi, *alo, *wqhi, *wqlo, *wohi, *wolo;
    cudaGetSymbolAddress((void**)&qkv,  g_qkv);
    cudaGetSymbolAddress((void**)&q,    g_q);
    cudaGetSymbolAddress((void**)&k,    g_k);
    cudaGetSymbolAddress((void**)&v,    g_v);
    cudaGetSymbolAddress((void**)&attn, g_attn);
    cudaGetSymbolAddress((void**)&xhi,  g_xhi);
    cudaGetSymbolAddress((void**)&xlo,  g_xlo);
    cudaGetSymbolAddress((void**)&ahi,  g_ahi);
    cudaGetSymbolAddress((void**)&alo,  g_alo);
    cudaGetSymbolAddress((void**)&wqhi, g_wqhi);
    cudaGetSymbolAddress((void**)&wqlo, g_wqlo);
    cudaGetSymbolAddress((void**)&wohi, g_wohi);
    cudaGetSymbolAddress((void**)&wolo, g_wolo);

    cudaFuncSetAttribute(gemm_mma_kernel,
                         cudaFuncAttributeMaxDynamicSharedMemorySize, GEMM_SMEM);
    const int fa_smem = (64 * 128 + 128 * 64 + 64 * 128 + 64 * 64) * (int)sizeof(float);
    cudaFuncSetAttribute(flash_attn_kernel,
                         cudaFuncAttributeMaxDynamicSharedMemorySize, fa_smem);

    // prep: weights transpose+split, activations split
    wtrans_kernel<<<dim3(NQKV / 32, KDIM / 32), dim3(32, 8)>>>(Wqkv, wqhi, wqlo, NQKV);
    wtrans_kernel<<<dim3(EMB / 32, KDIM / 32), dim3(32, 8)>>>(Wo, wohi, wolo, EMB);
    cvt_hilo_kernel<<<(MTOT * EMB / 4 + 255) / 256, 256>>>(x, xhi, xlo, MTOT * EMB / 4);

    // 1) QKV projection (mma.sync split-bf16)
    gemm_mma_kernel<<<dim3(NQKV / 128, MTOT / 128), 256, GEMM_SMEM>>>(
        xhi, xlo, wqhi, wqlo, bqkv, qkv, NQKV);

    // 2) RoPE + split
    rope_split_kernel<<<(MTOT * HEADS * 64) / 256, 256>>>(qkv, q, k, v);

    // 3) Causal flash attention (fp32)
    flash_attn_kernel<<<dim3(SEQ / 64, BHT), 256, fa_smem>>>(q, k, v, attn);

    // 4) Output projection (mma.sync split-bf16)
    cvt_hilo_kernel<<<(MTOT * EMB / 4 + 255) / 256, 256>>>(attn, ahi, alo, MTOT * EMB / 4);
    gemm_mma_kernel<<<dim3(EMB / 128, MTOT / 128), 256, GEMM_SMEM>>>(
        ahi, alo, wohi, wolo, bo, out, EMB);
}

// round 5
// speedup vs baseline: 3.1969x; 1.7957x over previous
#include <cuda_runtime.h>
#include <cuda_bf16.h>
#include <math.h>
#include <float.h>
#include <stdint.h>

// ---------------------------------------------------------------------------
// Problem constants
// ---------------------------------------------------------------------------
#define BATCH 2
#define SEQ   2048
#define EMB   2048
#define HEADS 16
#define DHEAD 128
#define MTOT  (BATCH*SEQ)     // 4096
#define NQKV  (3*EMB)         // 6144
#define BHT   (BATCH*HEADS)   // 32
#define KDIM  2048

// ---------------------------------------------------------------------------
// Global scratch (no cudaMalloc allowed)
// ---------------------------------------------------------------------------
__device__ float g_qkv [(size_t)MTOT * NQKV];

__device__ __nv_bfloat16 g_qhi[(size_t)BHT * SEQ * DHEAD];
__device__ __nv_bfloat16 g_qlo[(size_t)BHT * SEQ * DHEAD];
__device__ __nv_bfloat16 g_khi[(size_t)BHT * SEQ * DHEAD];
__device__ __nv_bfloat16 g_klo[(size_t)BHT * SEQ * DHEAD];
__device__ __nv_bfloat16 g_vhi[(size_t)BHT * SEQ * DHEAD];
__device__ __nv_bfloat16 g_vlo[(size_t)BHT * SEQ * DHEAD];

__device__ __nv_bfloat16 g_xhi[(size_t)MTOT * EMB];
__device__ __nv_bfloat16 g_xlo[(size_t)MTOT * EMB];
__device__ __nv_bfloat16 g_ahi[(size_t)MTOT * EMB];
__device__ __nv_bfloat16 g_alo[(size_t)MTOT * EMB];
__device__ __nv_bfloat16 g_wqhi[(size_t)NQKV * KDIM];
__device__ __nv_bfloat16 g_wqlo[(size_t)NQKV * KDIM];
__device__ __nv_bfloat16 g_wohi[(size_t)EMB * KDIM];
__device__ __nv_bfloat16 g_wolo[(size_t)EMB * KDIM];

// ---------------------------------------------------------------------------
// PTX helpers (sm_100 BASELINE only)
// ---------------------------------------------------------------------------
__device__ __forceinline__ uint32_t smem_u32(const void* p) {
    uint32_t a;
    asm("{ .reg .u64 t; cvta.to.shared.u64 t, %1; cvt.u32.u64 %0, t; }" : "=r"(a) : "l"(p));
    return a;
}
__device__ __forceinline__ void cp16(uint32_t s, const void* g) {
    asm volatile("cp.async.cg.shared.global [%0], [%1], 16;" :: "r"(s), "l"(g));
}
#define CP_COMMIT() asm volatile("cp.async.commit_group;" ::: "memory")
#define CP_WAIT(N)  asm volatile("cp.async.wait_group %0;" :: "n"(N) : "memory")

__device__ __forceinline__ void ldsm_x4(uint32_t r[4], uint32_t addr) {
    asm volatile("ldmatrix.sync.aligned.m8n8.x4.shared.b16 {%0,%1,%2,%3}, [%4];"
                 : "=r"(r[0]), "=r"(r[1]), "=r"(r[2]), "=r"(r[3]) : "r"(addr));
}
__device__ __forceinline__ void ldsm_x4_t(uint32_t r[4], uint32_t addr) {
    asm volatile("ldmatrix.sync.aligned.m8n8.x4.trans.shared.b16 {%0,%1,%2,%3}, [%4];"
                 : "=r"(r[0]), "=r"(r[1]), "=r"(r[2]), "=r"(r[3]) : "r"(addr));
}
__device__ __forceinline__ void mma_bf16(float c[4], const uint32_t a[4],
                                         uint32_t b0, uint32_t b1) {
    asm volatile("mma.sync.aligned.m16n8k16.row.col.f32.bf16.bf16.f32 "
                 "{%0,%1,%2,%3}, {%4,%5,%6,%7}, {%8,%9}, {%0,%1,%2,%3};"
                 : "+f"(c[0]), "+f"(c[1]), "+f"(c[2]), "+f"(c[3])
                 : "r"(a[0]), "r"(a[1]), "r"(a[2]), "r"(a[3]), "r"(b0), "r"(b1));
}
__device__ __forceinline__ float ex2f(float x) {
    float y; asm("ex2.approx.ftz.f32 %0, %1;" : "=f"(y) : "f"(x)); return y;
}
__device__ __forceinline__ uint32_t pack_bf16x2(float a, float b) {
    __nv_bfloat162 t = __floats2bfloat162_rn(a, b);
    return *reinterpret_cast<uint32_t*>(&t);
}

// ---------------------------------------------------------------------------
// Split-bf16 GEMM via mma.sync (unchanged from R4; tensor=69.8% measured)
// ---------------------------------------------------------------------------
#define GBK 64
#define NCHUNK (KDIM / GBK)
#define MAT_BYTES 16384
#define STAGE_BYTES (4 * MAT_BYTES)
#define GEMM_SMEM (2 * STAGE_BYTES)

__device__ __forceinline__ void load_stage(uint32_t st,
    const __nv_bfloat16* __restrict__ Ah, const __nv_bfloat16* __restrict__ Al,
    const __nv_bfloat16* __restrict__ Bh, const __nv_bfloat16* __restrict__ Bl,
    int k0, int tid)
{
#pragma unroll
    for (int i = 0; i < 16; i++) {
        int c   = tid + (i << 8);
        int row = (c & 1023) >> 3;
        int u   = c & 7;
        size_t   goff = (size_t)row * KDIM + k0 + u * 8;
        uint32_t soff = row * 128 + ((u ^ (row & 7)) << 4);
        const __nv_bfloat16* g; uint32_t mb;
        switch (i >> 2) {
            case 0:  g = Ah; mb = 0;             break;
            case 1:  g = Al; mb = MAT_BYTES;     break;
            case 2:  g = Bh; mb = 2 * MAT_BYTES; break;
            default: g = Bl; mb = 3 * MAT_BYTES; break;
        }
        cp16(st + mb + soff, g + goff);
    }
}

__device__ __forceinline__ void compute_chunk(uint32_t st, int lane, int wm, int wn,
                                              float acc[2][8][4])
{
    const int aRow0 = wm * 32 + ((lane >> 3) & 1) * 8 + (lane & 7);
    const int bRow0 = wn * 64 + ((lane >> 4) << 3) + (lane & 7);
    const int au = (lane >> 4);
    const int bu = ((lane >> 3) & 1);
#pragma unroll
    for (int ks = 0; ks < 4; ks++) {
        uint32_t ah[2][4], al[2][4];
#pragma unroll
        for (int mt = 0; mt < 2; mt++) {
            int row = aRow0 + mt * 16;
            int u   = ks * 2 + au;
            uint32_t off = row * 128 + ((u ^ (row & 7)) << 4);
            ldsm_x4(ah[mt], st + off);
            ldsm_x4(al[mt], st + MAT_BYTES + off);
        }
        uint32_t bh[4][4], bl[4][4];
#pragma unroll
        for (int ng = 0; ng < 4; ng++) {
            int row = bRow0 + ng * 16;
            int u   = ks * 2 + bu;
            uint32_t off = row * 128 + ((u ^ (row & 7)) << 4);
            ldsm_x4(bh[ng], st + 2 * MAT_BYTES + off);
            ldsm_x4(bl[ng], st + 3 * MAT_BYTES + off);
        }
#pragma unroll
        for (int mt = 0; mt < 2; mt++)
#pragma unroll
            for (int ng = 0; ng < 4; ng++) {
                mma_bf16(acc[mt][ng * 2],     ah[mt], bh[ng][0], bh[ng][1]);
                mma_bf16(acc[mt][ng * 2],     al[mt], bh[ng][0], bh[ng][1]);
                mma_bf16(acc[mt][ng * 2],     ah[mt], bl[ng][0], bl[ng][1]);
                mma_bf16(acc[mt][ng * 2 + 1], ah[mt], bh[ng][2], bh[ng][3]);
                mma_bf16(acc[mt][ng * 2 + 1], al[mt], bh[ng][2], bh[ng][3]);
                mma_bf16(acc[mt][ng * 2 + 1], ah[mt], bl[ng][2], bl[ng][3]);
            }
    }
}

__global__ __launch_bounds__(256)
void gemm_mma_kernel(const __nv_bfloat16* __restrict__ Ahi, const __nv_bfloat16* __restrict__ Alo,
                     const __nv_bfloat16* __restrict__ Bhi, const __nv_bfloat16* __restrict__ Blo,
                     const float* __restrict__ bias, float* __restrict__ C, int Nt)
{
    extern __shared__ __align__(1024) char sm[];
    const uint32_t sbase = smem_u32(sm);
    const int tid  = threadIdx.x;
    const int lane = tid & 31;
    const int wid  = tid >> 5;
    const int wm   = wid & 3;
    const int wn   = wid >> 2;
    const int m0 = blockIdx.y * 128;
    const int n0 = blockIdx.x * 128;

    const __nv_bfloat16* Ahb = Ahi + (size_t)m0 * KDIM;
    const __nv_bfloat16* Alb = Alo + (size_t)m0 * KDIM;
    const __nv_bfloat16* Bhb = Bhi + (size_t)n0 * KDIM;
    const __nv_bfloat16* Blb = Blo + (size_t)n0 * KDIM;

    float acc[2][8][4];
#pragma unroll
    for (int a = 0; a < 2; a++)
#pragma unroll
        for (int b = 0; b < 8; b++)
#pragma unroll
            for (int c = 0; c < 4; c++) acc[a][b][c] = 0.f;

    load_stage(sbase, Ahb, Alb, Bhb, Blb, 0, tid);
    CP_COMMIT();

    for (int c = 0; c < NCHUNK; c++) {
        if (c + 1 < NCHUNK) {
            load_stage(sbase + ((c + 1) & 1) * STAGE_BYTES,
                       Ahb, Alb, Bhb, Blb, (c + 1) * GBK, tid);
            CP_COMMIT();
            CP_WAIT(1);
        } else {
            CP_WAIT(0);
        }
        __syncthreads();
        compute_chunk(sbase + (c & 1) * STAGE_BYTES, lane, wm, wn, acc);
        __syncthreads();
    }

    const int g   = lane >> 2;
    const int tg2 = (lane & 3) * 2;
#pragma unroll
    for (int mt = 0; mt < 2; mt++) {
        int r0 = m0 + wm * 32 + mt * 16 + g;
#pragma unroll
        for (int ng = 0; ng < 8; ng++) {
            int col = n0 + wn * 64 + ng * 8 + tg2;
            float b0 = bias[col], b1 = bias[col + 1];
            float2 v0 = make_float2(acc[mt][ng][0] + b0, acc[mt][ng][1] + b1);
            float2 v1 = make_float2(acc[mt][ng][2] + b0, acc[mt][ng][3] + b1);
            *(float2*)&C[(size_t)r0 * Nt + col]       = v0;
            *(float2*)&C[(size_t)(r0 + 8) * Nt + col] = v1;
        }
    }
}

// ---------------------------------------------------------------------------
// Prep kernels (unchanged)
// ---------------------------------------------------------------------------
__global__ void wtrans_kernel(const float* __restrict__ W,
                              __nv_bfloat16* __restrict__ Whi,
                              __nv_bfloat16* __restrict__ Wlo, int Nt)
{
    __shared__ float t[32][33];
    const int tx = threadIdx.x, ty = threadIdx.y;
    const int n0 = blockIdx.x * 32, k0 = blockIdx.y * 32;
#pragma unroll
    for (int i = 0; i < 32; i += 8)
        t[ty + i][tx] = W[(size_t)(k0 + ty + i) * Nt + n0 + tx];
    __syncthreads();
#pragma unroll
    for (int i = 0; i < 32; i += 8) {
        float v = t[tx][ty + i];
        __nv_bfloat16 h = __float2bfloat16(v);
        __nv_bfloat16 l = __float2bfloat16(v - __bfloat162float(h));
        size_t o = (size_t)(n0 + ty + i) * KDIM + k0 + tx;
        Whi[o] = h; Wlo[o] = l;
    }
}

__global__ __launch_bounds__(256)
void cvt_hilo_kernel(const float* __restrict__ X,
                     __nv_bfloat16* __restrict__ Hi, __nv_bfloat16* __restrict__ Lo, int n4)
{
    int i = blockIdx.x * 256 + threadIdx.x;
    if (i >= n4) return;
    float4 v = ((const float4*)X)[i];
    union { __nv_bfloat16 b[4]; uint2 u; } hh, ll;
    float f[4] = {v.x, v.y, v.z, v.w};
#pragma unroll
    for (int j = 0; j < 4; j++) {
        hh.b[j] = __float2bfloat16(f[j]);
        ll.b[j] = __float2bfloat16(f[j] - __bfloat162float(hh.b[j]));
    }
    ((uint2*)Hi)[i] = hh.u;
    ((uint2*)Lo)[i] = ll.u;
}

// ---------------------------------------------------------------------------
// RoPE + split + head transpose -> bf16 hi/lo Q, K, V (layout [bh][seq][128])
// ---------------------------------------------------------------------------
__global__ __launch_bounds__(256)
void rope_split_kernel(const float* __restrict__ qkv,
                       __nv_bfloat16* __restrict__ Qh, __nv_bfloat16* __restrict__ Ql,
                       __nv_bfloat16* __restrict__ Kh, __nv_bfloat16* __restrict__ Kl,
                       __nv_bfloat16* __restrict__ Vh, __nv_bfloat16* __restrict__ Vl)
{
    int idx = blockIdx.x * 256 + threadIdx.x;
    if (idx >= MTOT * HEADS * 64) return;
    int j = idx & 63;
    int h = (idx >> 6) & (HEADS - 1);
    int t = idx >> 10;
    int n = t & (SEQ - 1);
    int b = t >> 11;

    const float* base = qkv + (size_t)t * NQKV + h * DHEAD;
    float q1 = base[j],           q2 = base[j + 64];
    float k1 = base[EMB + j],     k2 = base[EMB + j + 64];
    float v1 = base[2 * EMB + j], v2 = base[2 * EMB + j + 64];

    float pf = __bfloat162float(__float2bfloat16(
                   (float)pow(10000.0, (double)j * (1.0 / 64.0))));
    float th = __bfloat162float(__float2bfloat16(1.0f / pf));
    float fr = (float)n * th;
    float sn, cs;
    sincosf(fr, &sn, &cs);

    float qa = q1 * cs - q2 * sn, qb2 = q1 * sn + q2 * cs;
    float ka = k1 * cs - k2 * sn, kb2 = k1 * sn + k2 * cs;

    size_t o = ((size_t)(b * HEADS + h) * SEQ + n) * DHEAD + j;
#define SPLIT_STORE(HI, LO, off, val) { \
        __nv_bfloat16 _h = __float2bfloat16(val); \
        (HI)[off] = _h; (LO)[off] = __float2bfloat16((val) - __bfloat162float(_h)); }
    SPLIT_STORE(Qh, Ql, o,      qa);
    SPLIT_STORE(Qh, Ql, o + 64, qb2);
    SPLIT_STORE(Kh, Kl, o,      ka);
    SPLIT_STORE(Kh, Kl, o + 64, kb2);
    SPLIT_STORE(Vh, Vl, o,      v1);
    SPLIT_STORE(Vh, Vl, o + 64, v2);
#undef SPLIT_STORE
}

// ---------------------------------------------------------------------------
// Flash attention via mma.sync split-bf16. BM=128 (8 warps x m16), BN=64.
// smem: Q hi/lo [128][128] bf16 (64KB) + double-buffered KV stage
// (Khi,Klo,Vhi,Vlo each [64][128] bf16 = 64KB/stage). Total 192KB.
// Row = 256B = 16 x 16B units, swizzled u^(row&7).
// Output written directly as hi/lo bf16 in [B,N,H*128] (out-proj A layout).
// ---------------------------------------------------------------------------
#define FA_QBYTES   32768
#define FA_KVMAT    16384
#define FA_STAGE    (4 * FA_KVMAT)
#define FA_SMEM     (2 * FA_QBYTES + 2 * FA_STAGE)   // 196608

__device__ __forceinline__ void fa_load_kv(uint32_t st,
    const __nv_bfloat16* kh, const __nv_bfloat16* kl,
    const __nv_bfloat16* vh, const __nv_bfloat16* vl, int tid)
{
#pragma unroll
    for (int i = 0; i < 4; i++) {
        int uid = tid + (i << 8);
        int r = uid >> 4, u = uid & 15;
        uint32_t so = r * 256 + ((u ^ (r & 7)) << 4);
        size_t go = (size_t)r * 128 + u * 8;
        cp16(st + so,                kh + go);
        cp16(st + FA_KVMAT + so,     kl + go);
        cp16(st + 2 * FA_KVMAT + so, vh + go);
        cp16(st + 3 * FA_KVMAT + so, vl + go);
    }
}

__global__ __launch_bounds__(256)
void flash_mma_kernel(const __nv_bfloat16* __restrict__ Qh, const __nv_bfloat16* __restrict__ Ql,
                      const __nv_bfloat16* __restrict__ Kh, const __nv_bfloat16* __restrict__ Kl,
                      const __nv_bfloat16* __restrict__ Vh, const __nv_bfloat16* __restrict__ Vl,
                      __nv_bfloat16* __restrict__ Ohi, __nv_bfloat16* __restrict__ Olo)
{
    extern __shared__ __align__(1024) char sm[];
    const uint32_t sb = smem_u32(sm);
    const int tid = threadIdx.x, lane = tid & 31, w = tid >> 5;
    const int qb = gridDim.x - 1 - blockIdx.x;     // big-work CTAs first
    const int bh = blockIdx.y;
    const int row_lo = qb * 128 + w * 16;
    const uint32_t sQh = sb, sQl = sb + FA_QBYTES;
    const uint32_t sKV = sb + 2 * FA_QBYTES;

    // Load Q tile (128x128 hi/lo)
    {
        const __nv_bfloat16* qhg = Qh + ((size_t)bh * SEQ + qb * 128) * DHEAD;
        const __nv_bfloat16* qlg = Ql + ((size_t)bh * SEQ + qb * 128) * DHEAD;
#pragma unroll
        for (int i = 0; i < 8; i++) {
            int uid = tid + (i << 8);
            int r = uid >> 4, u = uid & 15;
            uint32_t so = r * 256 + ((u ^ (r & 7)) << 4);
            size_t go = (size_t)r * 128 + u * 8;
            cp16(sQh + so, qhg + go);
            cp16(sQl + so, qlg + go);
        }
    }
    const __nv_bfloat16* khb = Kh + (size_t)bh * SEQ * DHEAD;
    const __nv_bfloat16* klb = Kl + (size_t)bh * SEQ * DHEAD;
    const __nv_bfloat16* vhb = Vh + (size_t)bh * SEQ * DHEAD;
    const __nv_bfloat16* vlb = Vl + (size_t)bh * SEQ * DHEAD;

    fa_load_kv(sKV, khb, klb, vhb, vlb, tid);    // tile 0 (same group as Q)
    CP_COMMIT();

    float O[16][4];
#pragma unroll
    for (int i = 0; i < 16; i++)
#pragma unroll
        for (int j = 0; j < 4; j++) O[i][j] = 0.f;
    float mrow0 = -1e30f, mrow1 = -1e30f, lrow0 = 0.f, lrow1 = 0.f;

    const float SC = 0.08838834764831845f * 1.4426950408889634f;  // scale*log2(e)
    const int nkb = 2 * qb + 2;

    for (int kb = 0; kb < nkb; kb++) {
        const uint32_t st = sKV + (kb & 1) * FA_STAGE;
        if (kb + 1 < nkb) {
            fa_load_kv(sKV + ((kb + 1) & 1) * FA_STAGE,
                       khb + (size_t)(kb + 1) * 64 * DHEAD, klb + (size_t)(kb + 1) * 64 * DHEAD,
                       vhb + (size_t)(kb + 1) * 64 * DHEAD, vlb + (size_t)(kb + 1) * 64 * DHEAD, tid);
            CP_COMMIT();
            CP_WAIT(1);
        } else {
            CP_WAIT(0);
        }
        __syncthreads();

        const bool skip = (kb * 64 > row_lo + 15);   // tile fully above diagonal for this warp
        if (!skip) {
            // ---- S = Q @ K^T (3-pass split) ----
            float S[8][4];
#pragma unroll
            for (int i = 0; i < 8; i++)
#pragma unroll
                for (int j = 0; j < 4; j++) S[i][j] = 0.f;

            const int ar = w * 16 + (lane & 7) + ((lane >> 3) & 1) * 8;
            const int br_ = ((lane >> 4) << 3) + (lane & 7);
            const int au = (lane >> 4);
            const int bu = ((lane >> 3) & 1);
#pragma unroll
            for (int ks = 0; ks < 8; ks++) {
                uint32_t qa[4], ql4[4];
                uint32_t aoff = ar * 256 + (((2 * ks + au) ^ (ar & 7)) << 4);
                ldsm_x4(qa, sQh + aoff);
                ldsm_x4(ql4, sQl + aoff);
#pragma unroll
                for (int ng = 0; ng < 4; ng++) {
                    int br = ng * 16 + br_;
                    uint32_t boff = br * 256 + (((2 * ks + bu) ^ (br & 7)) << 4);
                    uint32_t kh4[4], kl4[4];
                    ldsm_x4(kh4, st + boff);
                    ldsm_x4(kl4, st + FA_KVMAT + boff);
                    mma_bf16(S[2 * ng],     qa,  kh4[0], kh4[1]);
                    mma_bf16(S[2 * ng],     ql4, kh4[0], kh4[1]);
                    mma_bf16(S[2 * ng],     qa,  kl4[0], kl4[1]);
                    mma_bf16(S[2 * ng + 1], qa,  kh4[2], kh4[3]);
                    mma_bf16(S[2 * ng + 1], ql4, kh4[2], kh4[3]);
                    mma_bf16(S[2 * ng + 1], qa,  kl4[2], kl4[3]);
                }
            }

            // ---- scale + causal mask + online softmax (base-2) ----
            const int r0 = row_lo + (lane >> 2), r1 = r0 + 8;
            const int c00 = kb * 64 + (lane & 3) * 2;
            float m0p = -1e30f, m1p = -1e30f;
#pragma unroll
            for (int nt = 0; nt < 8; nt++) {
                int c = c00 + nt * 8;
#pragma unroll
                for (int j = 0; j < 4; j++) {
                    int col = c + (j & 1);
                    int row = (j < 2) ? r0 : r1;
                    float s = S[nt][j] * SC;
                    if (col > row) s = -1e30f;
                    S[nt][j] = s;
                }
                m0p = fmaxf(m0p, fmaxf(S[nt][0], S[nt][1]));
                m1p = fmaxf(m1p, fmaxf(S[nt][2], S[nt][3]));
            }
            m0p = fmaxf(m0p, __shfl_xor_sync(0xffffffffu, m0p, 1));
            m0p = fmaxf(m0p, __shfl_xor_sync(0xffffffffu, m0p, 2));
            m1p = fmaxf(m1p, __shfl_xor_sync(0xffffffffu, m1p, 1));
            m1p = fmaxf(m1p, __shfl_xor_sync(0xffffffffu, m1p, 2));
            const float mn0 = fmaxf(mrow0, m0p), mn1 = fmaxf(mrow1, m1p);
            const float a0 = ex2f(mrow0 - mn0), a1 = ex2f(mrow1 - mn1);
            mrow0 = mn0; mrow1 = mn1;
            float ps0 = 0.f, ps1 = 0.f;
#pragma unroll
            for (int nt = 0; nt < 8; nt++) {
                S[nt][0] = ex2f(S[nt][0] - mn0);
                S[nt][1] = ex2f(S[nt][1] - mn0);
                S[nt][2] = ex2f(S[nt][2] - mn1);
                S[nt][3] = ex2f(S[nt][3] - mn1);
                ps0 += S[nt][0] + S[nt][1];
                ps1 += S[nt][2] + S[nt][3];
            }
            lrow0 = lrow0 * a0 + ps0;
            lrow1 = lrow1 * a1 + ps1;
#pragma unroll
            for (int dt = 0; dt < 16; dt++) {
                O[dt][0] *= a0; O[dt][1] *= a0;
                O[dt][2] *= a1; O[dt][3] *= a1;
            }

            // ---- O += P @ V (3-pass split; V^T via ldmatrix.trans) ----
            const int vr_ = (lane & 7) + ((lane >> 3) & 1) * 8;
            const int vu_ = (lane >> 4);
#pragma unroll
            for (int ks2 = 0; ks2 < 4; ks2++) {
                uint32_t ph[4], pl[4];
                {
                    float p0 = S[2 * ks2][0], p1 = S[2 * ks2][1];
                    float p2 = S[2 * ks2][2], p3 = S[2 * ks2][3];
                    float p4 = S[2 * ks2 + 1][0], p5 = S[2 * ks2 + 1][1];
                    float p6 = S[2 * ks2 + 1][2], p7 = S[2 * ks2 + 1][3];
                    ph[0] = pack_bf16x2(p0, p1);
                    ph[1] = pack_bf16x2(p2, p3);
                    ph[2] = pack_bf16x2(p4, p5);
                    ph[3] = pack_bf16x2(p6, p7);
#define RES(x) ((x) - __bfloat162float(__float2bfloat16(x)))
                    pl[0] = pack_bf16x2(RES(p0), RES(p1));
                    pl[1] = pack_bf16x2(RES(p2), RES(p3));
                    pl[2] = pack_bf16x2(RES(p4), RES(p5));
                    pl[3] = pack_bf16x2(RES(p6), RES(p7));
#undef RES
                }
                int vr = ks2 * 16 + vr_;
#pragma unroll
                for (int dp = 0; dp < 8; dp++) {
                    uint32_t voff = vr * 256 + (((dp * 2 + vu_) ^ (vr & 7)) << 4);
                    uint32_t vh4[4], vl4[4];
                    ldsm_x4_t(vh4, st + 2 * FA_KVMAT + voff);
                    ldsm_x4_t(vl4, st + 3 * FA_KVMAT + voff);
                    mma_bf16(O[2 * dp],     ph, vh4[0], vh4[1]);
                    mma_bf16(O[2 * dp],     pl, vh4[0], vh4[1]);
                    mma_bf16(O[2 * dp],     ph, vl4[0], vl4[1]);
                    mma_bf16(O[2 * dp + 1], ph, vh4[2], vh4[3]);
                    mma_bf16(O[2 * dp + 1], pl, vh4[2], vh4[3]);
                    mma_bf16(O[2 * dp + 1], ph, vl4[2], vl4[3]);
                }
            }
        }
        __syncthreads();
    }

    // ---- epilogue: normalize, split hi/lo, store in out-proj A layout ----
    float l0 = lrow0;
    l0 += __shfl_xor_sync(0xffffffffu, l0, 1);
    l0 += __shfl_xor_sync(0xffffffffu, l0, 2);
    float l1 = lrow1;
    l1 += __shfl_xor_sync(0xffffffffu, l1, 1);
    l1 += __shfl_xor_sync(0xffffffffu, l1, 2);
    const float inv0 = 1.0f / l0, inv1 = 1.0f / l1;

    const int b = bh >> 4, h = bh & 15;
    const int n0r = row_lo + (lane >> 2);
    size_t base0 = ((size_t)(b * SEQ + n0r)) * EMB + h * DHEAD + (lane & 3) * 2;
    size_t base1 = base0 + (size_t)8 * EMB;
#pragma unroll
    for (int dt = 0; dt < 16; dt++) {
        float x0 = O[dt][0] * inv0, x1 = O[dt][1] * inv0;
        float x2 = O[dt][2] * inv1, x3 = O[dt][3] * inv1;
        float h0 = __bfloat162float(__float2bfloat16(x0));
        float h1 = __bfloat162float(__float2bfloat16(x1));
        float h2 = __bfloat162float(__float2bfloat16(x2));
        float h3 = __bfloat162float(__float2bfloat16(x3));
        *(uint32_t*)&Ohi[base0 + dt * 8] = pack_bf16x2(x0, x1);
        *(uint32_t*)&Olo[base0 + dt * 8] = pack_bf16x2(x0 - h0, x1 - h1);
        *(uint32_t*)&Ohi[base1 + dt * 8] = pack_bf16x2(x2, x3);
        *(uint32_t*)&Olo[base1 + dt * 8] = pack_bf16x2(x2 - h2, x3 - h3);
    }
}

// ---------------------------------------------------------------------------
// Launch
// ---------------------------------------------------------------------------
extern "C" void kernel_launch(void* const* d_in, const int* in_sizes, int n_in,
                              void* d_out, int out_size)
{
    const float* x    = (const float*)d_in[0];
    const float* Wqkv = (const float*)d_in[1];
    const float* bqkv = (const float*)d_in[2];
    const float* Wo   = (const float*)d_in[3];
    const float* bo   = (const float*)d_in[4];
    float* out = (float*)d_out;
    (void)in_sizes; (void)n_in; (void)out_size;

    float* qkv;
    __nv_bfloat16 *qhi, *qlo, *khi, *klo, *vhi, *vlo;
    __nv_bfloat16 *xhi, *xlo, *ahi, *alo, *wqhi, *wqlo, *wohi, *wolo;
    cudaGetSymbolAddress((void**)&qkv,  g_qkv);
    cudaGetSymbolAddress((void**)&qhi,  g_qhi);
    cudaGetSymbolAddress((void**)&qlo,  g_qlo);
    cudaGetSymbolAddress((void**)&khi,  g_khi);
    cudaGetSymbolAddress((void**)&klo,  g_klo);
    cudaGetSymbolAddress((void**)&vhi,  g_vhi);
    cudaGetSymbolAddress((void**)&vlo,  g_vlo);
    cudaGetSymbolAddress((void**)&xhi,  g_xhi);
    cudaGetSymbolAddress((void**)&xlo,  g_xlo);
    cudaGetSymbolAddress((void**)&ahi,  g_ahi);
    cudaGetSymbolAddress((void**)&alo,  g_alo);
    cudaGetSymbolAddress((void**)&wqhi, g_wqhi);
    cudaGetSymbolAddress((void**)&wqlo, g_wqlo);
    cudaGetSymbolAddress((void**)&wohi, g_wohi);
    cudaGetSymbolAddress((void**)&wolo, g_wolo);

    cudaFuncSetAttribute(gemm_mma_kernel,
                         cudaFuncAttributeMaxDynamicSharedMemorySize, GEMM_SMEM);
    cudaFuncSetAttribute(flash_mma_kernel,
                         cudaFuncAttributeMaxDynamicSharedMemorySize, FA_SMEM);

    // prep
    wtrans_kernel<<<dim3(NQKV / 32, KDIM / 32), dim3(32, 8)>>>(Wqkv, wqhi, wqlo, NQKV);
    wtrans_kernel<<<dim3(EMB / 32, KDIM / 32), dim3(32, 8)>>>(Wo, wohi, wolo, EMB);
    cvt_hilo_kernel<<<(MTOT * EMB / 4 + 255) / 256, 256>>>(x, xhi, xlo, MTOT * EMB / 4);

    // 1) QKV projection
    gemm_mma_kernel<<<dim3(NQKV / 128, MTOT / 128), 256, GEMM_SMEM>>>(
        xhi, xlo, wqhi, wqlo, bqkv, qkv, NQKV);

    // 2) RoPE + split -> bf16 hi/lo Q,K,V
    rope_split_kernel<<<(MTOT * HEADS * 64) / 256, 256>>>(qkv, qhi, qlo, khi, klo, vhi, vlo);

    // 3) Flash attention (mma.sync split-bf16) -> writes out-proj A hi/lo directly
    flash_mma_kernel<<<dim3(SEQ / 128, BHT), 256, FA_SMEM>>>(
        qhi, qlo, khi, klo, vhi, vlo, ahi, alo);

    // 4) Output projection
    gemm_mma_kernel<<<dim3(EMB / 128, MTOT / 128), 256, GEMM_SMEM>>>(
        ahi, alo, wohi, wolo, bo, out, EMB);
}

// round 6
// speedup vs baseline: 3.4472x; 1.0783x over previous
#include <cuda_runtime.h>
#include <cuda_bf16.h>
#include <math.h>
#include <float.h>
#include <stdint.h>

// ---------------------------------------------------------------------------
// Problem constants
// ---------------------------------------------------------------------------
#define BATCH 2
#define SEQ   2048
#define EMB   2048
#define HEADS 16
#define DHEAD 128
#define MTOT  (BATCH*SEQ)     // 4096
#define NQKV  (3*EMB)         // 6144
#define BHT   (BATCH*HEADS)   // 32
#define KDIM  2048

// ---------------------------------------------------------------------------
// Global scratch
// ---------------------------------------------------------------------------
__device__ float g_qkv [(size_t)MTOT * NQKV];
__device__ float2 g_rope[(size_t)SEQ * 64];          // (cos, sin) per (n, j)

__device__ __nv_bfloat16 g_qhi[(size_t)BHT * SEQ * DHEAD];
__device__ __nv_bfloat16 g_qlo[(size_t)BHT * SEQ * DHEAD];
__device__ __nv_bfloat16 g_khi[(size_t)BHT * SEQ * DHEAD];
__device__ __nv_bfloat16 g_klo[(size_t)BHT * SEQ * DHEAD];
__device__ __nv_bfloat16 g_vhi[(size_t)BHT * SEQ * DHEAD];
__device__ __nv_bfloat16 g_vlo[(size_t)BHT * SEQ * DHEAD];

__device__ __nv_bfloat16 g_xhi[(size_t)MTOT * EMB];
__device__ __nv_bfloat16 g_xlo[(size_t)MTOT * EMB];
__device__ __nv_bfloat16 g_ahi[(size_t)MTOT * EMB];
__device__ __nv_bfloat16 g_alo[(size_t)MTOT * EMB];
__device__ __nv_bfloat16 g_wqhi[(size_t)NQKV * KDIM];
__device__ __nv_bfloat16 g_wqlo[(size_t)NQKV * KDIM];
__device__ __nv_bfloat16 g_wohi[(size_t)EMB * KDIM];
__device__ __nv_bfloat16 g_wolo[(size_t)EMB * KDIM];

// ---------------------------------------------------------------------------
// PTX helpers (sm_100 BASELINE only)
// ---------------------------------------------------------------------------
__device__ __forceinline__ uint32_t smem_u32(const void* p) {
    uint32_t a;
    asm("{ .reg .u64 t; cvta.to.shared.u64 t, %1; cvt.u32.u64 %0, t; }" : "=r"(a) : "l"(p));
    return a;
}
__device__ __forceinline__ void cp16(uint32_t s, const void* g) {
    asm volatile("cp.async.cg.shared.global [%0], [%1], 16;" :: "r"(s), "l"(g));
}
#define CP_COMMIT() asm volatile("cp.async.commit_group;" ::: "memory")
#define CP_WAIT(N)  asm volatile("cp.async.wait_group %0;" :: "n"(N) : "memory")

__device__ __forceinline__ void ldsm_x4(uint32_t r[4], uint32_t addr) {
    asm volatile("ldmatrix.sync.aligned.m8n8.x4.shared.b16 {%0,%1,%2,%3}, [%4];"
                 : "=r"(r[0]), "=r"(r[1]), "=r"(r[2]), "=r"(r[3]) : "r"(addr));
}
__device__ __forceinline__ void ldsm_x4_t(uint32_t r[4], uint32_t addr) {
    asm volatile("ldmatrix.sync.aligned.m8n8.x4.trans.shared.b16 {%0,%1,%2,%3}, [%4];"
                 : "=r"(r[0]), "=r"(r[1]), "=r"(r[2]), "=r"(r[3]) : "r"(addr));
}
__device__ __forceinline__ void mma_bf16(float c[4], const uint32_t a[4],
                                         uint32_t b0, uint32_t b1) {
    asm volatile("mma.sync.aligned.m16n8k16.row.col.f32.bf16.bf16.f32 "
                 "{%0,%1,%2,%3}, {%4,%5,%6,%7}, {%8,%9}, {%0,%1,%2,%3};"
                 : "+f"(c[0]), "+f"(c[1]), "+f"(c[2]), "+f"(c[3])
                 : "r"(a[0]), "r"(a[1]), "r"(a[2]), "r"(a[3]), "r"(b0), "r"(b1));
}
__device__ __forceinline__ float ex2f(float x) {
    float y; asm("ex2.approx.ftz.f32 %0, %1;" : "=f"(y) : "f"(x)); return y;
}
__device__ __forceinline__ uint32_t pack_bf16x2(float a, float b) {
    __nv_bfloat162 t = __floats2bfloat162_rn(a, b);
    return *reinterpret_cast<uint32_t*>(&t);
}

// ---------------------------------------------------------------------------
// Split-bf16 GEMM v2: BK=32, 3 smem stages, 1 sync/chunk, 2 CTAs/SM.
// C[M,Nt] = A[M,2048] @ B^T + bias; A row-major hi/lo, B K-major hi/lo.
// SMEM row = 32 bf16 = 64B = 4 x 16B units; swizzle u ^ ((row>>1)&3).
// ---------------------------------------------------------------------------
#define GBK2   32
#define NCH2   (KDIM / GBK2)       // 64
#define MATB2  8192                // 128 x 32 bf16
#define STAGE2 (4 * MATB2)         // 32768
#define GEMM_SMEM (3 * STAGE2)     // 98304

__device__ __forceinline__ void load_stage2(uint32_t st,
    const __nv_bfloat16* __restrict__ Ah, const __nv_bfloat16* __restrict__ Al,
    const __nv_bfloat16* __restrict__ Bh, const __nv_bfloat16* __restrict__ Bl,
    int k0, int tid)
{
#pragma unroll
    for (int i = 0; i < 2; i++) {
        int uid = tid + (i << 8);              // 0..511
        int r = uid >> 2, u = uid & 3;
        size_t   goff = (size_t)r * KDIM + k0 + u * 8;
        uint32_t soff = r * 64 + ((u ^ ((r >> 1) & 3)) << 4);
        cp16(st + soff,             Ah + goff);
        cp16(st + MATB2 + soff,     Al + goff);
        cp16(st + 2 * MATB2 + soff, Bh + goff);
        cp16(st + 3 * MATB2 + soff, Bl + goff);
    }
}

__device__ __forceinline__ void compute_chunk2(uint32_t st, int lane, int wm, int wn,
                                               float acc[2][8][4])
{
    const int aRow0 = wm * 32 + ((lane >> 3) & 1) * 8 + (lane & 7);
    const int bRow0 = wn * 64 + ((lane >> 4) << 3) + (lane & 7);
    const int au = (lane >> 4);
    const int bu = ((lane >> 3) & 1);
#pragma unroll
    for (int ks = 0; ks < 2; ks++) {
        uint32_t ah[2][4], al[2][4];
#pragma unroll
        for (int mt = 0; mt < 2; mt++) {
            int row = aRow0 + mt * 16;
            int u   = ks * 2 + au;
            uint32_t off = row * 64 + ((u ^ ((row >> 1) & 3)) << 4);
            ldsm_x4(ah[mt], st + off);
            ldsm_x4(al[mt], st + MATB2 + off);
        }
        uint32_t bh[4][4], bl[4][4];
#pragma unroll
        for (int ng = 0; ng < 4; ng++) {
            int row = bRow0 + ng * 16;
            int u   = ks * 2 + bu;
            uint32_t off = row * 64 + ((u ^ ((row >> 1) & 3)) << 4);
            ldsm_x4(bh[ng], st + 2 * MATB2 + off);
            ldsm_x4(bl[ng], st + 3 * MATB2 + off);
        }
#pragma unroll
        for (int mt = 0; mt < 2; mt++)
#pragma unroll
            for (int ng = 0; ng < 4; ng++) {
                mma_bf16(acc[mt][ng * 2],     ah[mt], bh[ng][0], bh[ng][1]);
                mma_bf16(acc[mt][ng * 2],     al[mt], bh[ng][0], bh[ng][1]);
                mma_bf16(acc[mt][ng * 2],     ah[mt], bl[ng][0], bl[ng][1]);
                mma_bf16(acc[mt][ng * 2 + 1], ah[mt], bh[ng][2], bh[ng][3]);
                mma_bf16(acc[mt][ng * 2 + 1], al[mt], bh[ng][2], bh[ng][3]);
                mma_bf16(acc[mt][ng * 2 + 1], ah[mt], bl[ng][2], bl[ng][3]);
            }
    }
}

__global__ __launch_bounds__(256, 2)
void gemm_mma_kernel(const __nv_bfloat16* __restrict__ Ahi, const __nv_bfloat16* __restrict__ Alo,
                     const __nv_bfloat16* __restrict__ Bhi, const __nv_bfloat16* __restrict__ Blo,
                     const float* __restrict__ bias, float* __restrict__ C, int Nt)
{
    extern __shared__ __align__(1024) char sm[];
    const uint32_t sbase = smem_u32(sm);
    const int tid  = threadIdx.x;
    const int lane = tid & 31;
    const int wid  = tid >> 5;
    const int wm   = wid & 3;
    const int wn   = wid >> 2;
    const int m0 = blockIdx.y * 128;
    const int n0 = blockIdx.x * 128;

    const __nv_bfloat16* Ahb = Ahi + (size_t)m0 * KDIM;
    const __nv_bfloat16* Alb = Alo + (size_t)m0 * KDIM;
    const __nv_bfloat16* Bhb = Bhi + (size_t)n0 * KDIM;
    const __nv_bfloat16* Blb = Blo + (size_t)n0 * KDIM;

    float acc[2][8][4];
#pragma unroll
    for (int a = 0; a < 2; a++)
#pragma unroll
        for (int b = 0; b < 8; b++)
#pragma unroll
            for (int c = 0; c < 4; c++) acc[a][b][c] = 0.f;

    // prologue: stages 0,1
    load_stage2(sbase,          Ahb, Alb, Bhb, Blb, 0, tid);
    CP_COMMIT();
    load_stage2(sbase + STAGE2, Ahb, Alb, Bhb, Blb, GBK2, tid);
    CP_COMMIT();

    uint32_t stage_off[3] = {0, STAGE2, 2 * STAGE2};
    for (int c = 0; c < NCH2; c++) {
        CP_WAIT(1);              // group c complete (group c+1 may pend)
        __syncthreads();         // visibility of other threads' cp.async; guards overwrite below
        compute_chunk2(sbase + stage_off[c % 3], lane, wm, wn, acc);
        // prefetch stage c+2 (overwrites stage (c-1)%3 — all warps passed the barrier above
        // after finishing compute of chunk c-1, so the buffer is free)
        if (c + 2 < NCH2)
            load_stage2(sbase + stage_off[(c + 2) % 3],
                        Ahb, Alb, Bhb, Blb, (c + 2) * GBK2, tid);
        CP_COMMIT();             // empty group at tail keeps wait-count accounting valid
    }

    const int g   = lane >> 2;
    const int tg2 = (lane & 3) * 2;
#pragma unroll
    for (int mt = 0; mt < 2; mt++) {
        int r0 = m0 + wm * 32 + mt * 16 + g;
#pragma unroll
        for (int ng = 0; ng < 8; ng++) {
            int col = n0 + wn * 64 + ng * 8 + tg2;
            float b0 = bias[col], b1 = bias[col + 1];
            float2 v0 = make_float2(acc[mt][ng][0] + b0, acc[mt][ng][1] + b1);
            float2 v1 = make_float2(acc[mt][ng][2] + b0, acc[mt][ng][3] + b1);
            *(float2*)&C[(size_t)r0 * Nt + col]       = v0;
            *(float2*)&C[(size_t)(r0 + 8) * Nt + col] = v1;
        }
    }
}

// ---------------------------------------------------------------------------
// Prep: vectorized weight transpose + split  W[K][Nt] fp32 -> hi/lo [Nt][K]
// ---------------------------------------------------------------------------
__global__ __launch_bounds__(256)
void wtrans_kernel(const float* __restrict__ W,
                   __nv_bfloat16* __restrict__ Whi,
                   __nv_bfloat16* __restrict__ Wlo, int Nt)
{
    __shared__ float t[32][33];
    const int tid = threadIdx.x;
    const int n0 = blockIdx.x * 32, k0 = blockIdx.y * 32;
    {
        int row = tid >> 3, c4 = (tid & 7) * 4;     // row = k index
        float4 v = *(const float4*)&W[(size_t)(k0 + row) * Nt + n0 + c4];
        t[row][c4] = v.x; t[row][c4 + 1] = v.y; t[row][c4 + 2] = v.z; t[row][c4 + 3] = v.w;
    }
    __syncthreads();
    {
        int n = tid >> 3, kc = (tid & 7) * 4;
        uint32_t hp[2], lp[2];
        float f0 = t[kc][n], f1 = t[kc + 1][n], f2 = t[kc + 2][n], f3 = t[kc + 3][n];
#define HI(x) __bfloat162float(__float2bfloat16(x))
        hp[0] = pack_bf16x2(f0, f1); hp[1] = pack_bf16x2(f2, f3);
        lp[0] = pack_bf16x2(f0 - HI(f0), f1 - HI(f1));
        lp[1] = pack_bf16x2(f2 - HI(f2), f3 - HI(f3));
#undef HI
        size_t o = (size_t)(n0 + n) * KDIM + k0 + kc;
        *(uint2*)&Whi[o] = make_uint2(hp[0], hp[1]);
        *(uint2*)&Wlo[o] = make_uint2(lp[0], lp[1]);
    }
}

__global__ __launch_bounds__(256)
void cvt_hilo_kernel(const float* __restrict__ X,
                     __nv_bfloat16* __restrict__ Hi, __nv_bfloat16* __restrict__ Lo, int n4)
{
    int i = blockIdx.x * 256 + threadIdx.x;
    if (i >= n4) return;
    float4 v = ((const float4*)X)[i];
    union { __nv_bfloat16 b[4]; uint2 u; } hh, ll;
    float f[4] = {v.x, v.y, v.z, v.w};
#pragma unroll
    for (int j = 0; j < 4; j++) {
        hh.b[j] = __float2bfloat16(f[j]);
        ll.b[j] = __float2bfloat16(f[j] - __bfloat162float(hh.b[j]));
    }
    ((uint2*)Hi)[i] = hh.u;
    ((uint2*)Lo)[i] = ll.u;
}

// ---------------------------------------------------------------------------
// RoPE sincos table: (n, j) -> (cos, sin). bf16 theta replication (reference).
// ---------------------------------------------------------------------------
__global__ __launch_bounds__(256)
void rope_table_kernel()
{
    int idx = blockIdx.x * 256 + threadIdx.x;
    if (idx >= SEQ * 64) return;
    int n = idx >> 6, j = idx & 63;
    float pf = __bfloat162float(__float2bfloat16(
                   (float)pow(10000.0, (double)j * (1.0 / 64.0))));
    float th = __bfloat162float(__float2bfloat16(1.0f / pf));
    float sn, cs;
    sincosf((float)n * th, &sn, &cs);
    g_rope[idx] = make_float2(cs, sn);
}

// ---------------------------------------------------------------------------
// RoPE + split + head transpose, vectorized (4 j's per thread, table lookup)
// ---------------------------------------------------------------------------
__global__ __launch_bounds__(256)
void rope_split_kernel(const float* __restrict__ qkv,
                       __nv_bfloat16* __restrict__ Qh, __nv_bfloat16* __restrict__ Ql,
                       __nv_bfloat16* __restrict__ Kh, __nv_bfloat16* __restrict__ Kl,
                       __nv_bfloat16* __restrict__ Vh, __nv_bfloat16* __restrict__ Vl)
{
    int idx = blockIdx.x * 256 + threadIdx.x;      // MTOT*HEADS*16
    if (idx >= MTOT * HEADS * 16) return;
    int j0 = (idx & 15) * 4;
    int h  = (idx >> 4) & (HEADS - 1);
    int t  = idx >> 8;
    int n  = t & (SEQ - 1);
    int b  = t >> 11;

    const float* base = qkv + (size_t)t * NQKV + h * DHEAD;
    float4 q1 = *(const float4*)(base + j0);
    float4 q2 = *(const float4*)(base + 64 + j0);
    float4 k1 = *(const float4*)(base + EMB + j0);
    float4 k2 = *(const float4*)(base + EMB + 64 + j0);
    float4 v1 = *(const float4*)(base + 2 * EMB + j0);
    float4 v2 = *(const float4*)(base + 2 * EMB + 64 + j0);

    const float4* tb = (const float4*)(g_rope + ((size_t)n << 6) + j0);
    float4 t0 = tb[0], t1 = tb[1];
    float cs[4] = {t0.x, t0.z, t1.x, t1.z};
    float sn[4] = {t0.y, t0.w, t1.y, t1.w};
    float qa[4] = {q1.x, q1.y, q1.z, q1.w}, qb[4] = {q2.x, q2.y, q2.z, q2.w};
    float ka[4] = {k1.x, k1.y, k1.z, k1.w}, kb[4] = {k2.x, k2.y, k2.z, k2.w};
    float va[4] = {v1.x, v1.y, v1.z, v1.w}, vb[4] = {v2.x, v2.y, v2.z, v2.w};

    float qo1[4], qo2[4], ko1[4], ko2[4];
#pragma unroll
    for (int i = 0; i < 4; i++) {
        qo1[i] = qa[i] * cs[i] - qb[i] * sn[i];
        qo2[i] = qa[i] * sn[i] + qb[i] * cs[i];
        ko1[i] = ka[i] * cs[i] - kb[i] * sn[i];
        ko2[i] = ka[i] * sn[i] + kb[i] * cs[i];
    }

    size_t o = ((size_t)(b * HEADS + h) * SEQ + n) * DHEAD + j0;
#define HI(x) __bfloat162float(__float2bfloat16(x))
#define ST4(HIP, LOP, off, f) { \
        *(uint2*)&(HIP)[off] = make_uint2(pack_bf16x2((f)[0], (f)[1]), pack_bf16x2((f)[2], (f)[3])); \
        *(uint2*)&(LOP)[off] = make_uint2(pack_bf16x2((f)[0]-HI((f)[0]), (f)[1]-HI((f)[1])), \
                                          pack_bf16x2((f)[2]-HI((f)[2]), (f)[3]-HI((f)[3]))); }
    ST4(Qh, Ql, o,      qo1);
    ST4(Qh, Ql, o + 64, qo2);
    ST4(Kh, Kl, o,      ko1);
    ST4(Kh, Kl, o + 64, ko2);
    ST4(Vh, Vl, o,      va);
    ST4(Vh, Vl, o + 64, vb);
#undef ST4
#undef HI
}

// ---------------------------------------------------------------------------
// Flash attention via mma.sync split-bf16 (unchanged from R5; ~190us measured)
// ---------------------------------------------------------------------------
#define FA_QBYTES   32768
#define FA_KVMAT    16384
#define FA_STAGE    (4 * FA_KVMAT)
#define FA_SMEM     (2 * FA_QBYTES + 2 * FA_STAGE)   // 196608

__device__ __forceinline__ void fa_load_kv(uint32_t st,
    const __nv_bfloat16* kh, const __nv_bfloat16* kl,
    const __nv_bfloat16* vh, const __nv_bfloat16* vl, int tid)
{
#pragma unroll
    for (int i = 0; i < 4; i++) {
        int uid = tid + (i << 8);
        int r = uid >> 4, u = uid & 15;
        uint32_t so = r * 256 + ((u ^ (r & 7)) << 4);
        size_t go = (size_t)r * 128 + u * 8;
        cp16(st + so,                kh + go);
        cp16(st + FA_KVMAT + so,     kl + go);
        cp16(st + 2 * FA_KVMAT + so, vh + go);
        cp16(st + 3 * FA_KVMAT + so, vl + go);
    }
}

__global__ __launch_bounds__(256)
void flash_mma_kernel(const __nv_bfloat16* __restrict__ Qh, const __nv_bfloat16* __restrict__ Ql,
                      const __nv_bfloat16* __restrict__ Kh, const __nv_bfloat16* __restrict__ Kl,
                      const __nv_bfloat16* __restrict__ Vh, const __nv_bfloat16* __restrict__ Vl,
                      __nv_bfloat16* __restrict__ Ohi, __nv_bfloat16* __restrict__ Olo)
{
    extern __shared__ __align__(1024) char sm[];
    const uint32_t sb = smem_u32(sm);
    const int tid = threadIdx.x, lane = tid & 31, w = tid >> 5;
    const int qb = gridDim.x - 1 - blockIdx.x;
    const int bh = blockIdx.y;
    const int row_lo = qb * 128 + w * 16;
    const uint32_t sQh = sb, sQl = sb + FA_QBYTES;
    const uint32_t sKV = sb + 2 * FA_QBYTES;

    {
        const __nv_bfloat16* qhg = Qh + ((size_t)bh * SEQ + qb * 128) * DHEAD;
        const __nv_bfloat16* qlg = Ql + ((size_t)bh * SEQ + qb * 128) * DHEAD;
#pragma unroll
        for (int i = 0; i < 8; i++) {
            int uid = tid + (i << 8);
            int r = uid >> 4, u = uid & 15;
            uint32_t so = r * 256 + ((u ^ (r & 7)) << 4);
            size_t go = (size_t)r * 128 + u * 8;
            cp16(sQh + so, qhg + go);
            cp16(sQl + so, qlg + go);
        }
    }
    const __nv_bfloat16* khb = Kh + (size_t)bh * SEQ * DHEAD;
    const __nv_bfloat16* klb = Kl + (size_t)bh * SEQ * DHEAD;
    const __nv_bfloat16* vhb = Vh + (size_t)bh * SEQ * DHEAD;
    const __nv_bfloat16* vlb = Vl + (size_t)bh * SEQ * DHEAD;

    fa_load_kv(sKV, khb, klb, vhb, vlb, tid);
    CP_COMMIT();

    float O[16][4];
#pragma unroll
    for (int i = 0; i < 16; i++)
#pragma unroll
        for (int j = 0; j < 4; j++) O[i][j] = 0.f;
    float mrow0 = -1e30f, mrow1 = -1e30f, lrow0 = 0.f, lrow1 = 0.f;

    const float SC = 0.08838834764831845f * 1.4426950408889634f;
    const int nkb = 2 * qb + 2;

    for (int kb = 0; kb < nkb; kb++) {
        const uint32_t st = sKV + (kb & 1) * FA_STAGE;
        if (kb + 1 < nkb) {
            fa_load_kv(sKV + ((kb + 1) & 1) * FA_STAGE,
                       khb + (size_t)(kb + 1) * 64 * DHEAD, klb + (size_t)(kb + 1) * 64 * DHEAD,
                       vhb + (size_t)(kb + 1) * 64 * DHEAD, vlb + (size_t)(kb + 1) * 64 * DHEAD, tid);
            CP_COMMIT();
            CP_WAIT(1);
        } else {
            CP_WAIT(0);
        }
        __syncthreads();

        const bool skip = (kb * 64 > row_lo + 15);
        if (!skip) {
            float S[8][4];
#pragma unroll
            for (int i = 0; i < 8; i++)
#pragma unroll
                for (int j = 0; j < 4; j++) S[i][j] = 0.f;

            const int ar = w * 16 + (lane & 7) + ((lane >> 3) & 1) * 8;
            const int br_ = ((lane >> 4) << 3) + (lane & 7);
            const int au = (lane >> 4);
            const int bu = ((lane >> 3) & 1);
#pragma unroll
            for (int ks = 0; ks < 8; ks++) {
                uint32_t qa[4], ql4[4];
                uint32_t aoff = ar * 256 + (((2 * ks + au) ^ (ar & 7)) << 4);
                ldsm_x4(qa, sQh + aoff);
                ldsm_x4(ql4, sQl + aoff);
#pragma unroll
                for (int ng = 0; ng < 4; ng++) {
                    int br = ng * 16 + br_;
                    uint32_t boff = br * 256 + (((2 * ks + bu) ^ (br & 7)) << 4);
                    uint32_t kh4[4], kl4[4];
                    ldsm_x4(kh4, st + boff);
                    ldsm_x4(kl4, st + FA_KVMAT + boff);
                    mma_bf16(S[2 * ng],     qa,  kh4[0], kh4[1]);
                    mma_bf16(S[2 * ng],     ql4, kh4[0], kh4[1]);
                    mma_bf16(S[2 * ng],     qa,  kl4[0], kl4[1]);
                    mma_bf16(S[2 * ng + 1], qa,  kh4[2], kh4[3]);
                    mma_bf16(S[2 * ng + 1], ql4, kh4[2], kh4[3]);
                    mma_bf16(S[2 * ng + 1], qa,  kl4[2], kl4[3]);
                }
            }

            const int r0 = row_lo + (lane >> 2), r1 = r0 + 8;
            const int c00 = kb * 64 + (lane & 3) * 2;
            float m0p = -1e30f, m1p = -1e30f;
#pragma unroll
            for (int nt = 0; nt < 8; nt++) {
                int c = c00 + nt * 8;
#pragma unroll
                for (int j = 0; j < 4; j++) {
                    int col = c + (j & 1);
                    int row = (j < 2) ? r0 : r1;
                    float s = S[nt][j] * SC;
                    if (col > row) s = -1e30f;
                    S[nt][j] = s;
                }
                m0p = fmaxf(m0p, fmaxf(S[nt][0], S[nt][1]));
                m1p = fmaxf(m1p, fmaxf(S[nt][2], S[nt][3]));
            }
            m0p = fmaxf(m0p, __shfl_xor_sync(0xffffffffu, m0p, 1));
            m0p = fmaxf(m0p, __shfl_xor_sync(0xffffffffu, m0p, 2));
            m1p = fmaxf(m1p, __shfl_xor_sync(0xffffffffu, m1p, 1));
            m1p = fmaxf(m1p, __shfl_xor_sync(0xffffffffu, m1p, 2));
            const float mn0 = fmaxf(mrow0, m0p), mn1 = fmaxf(mrow1, m1p);
            const float a0 = ex2f(mrow0 - mn0), a1 = ex2f(mrow1 - mn1);
            mrow0 = mn0; mrow1 = mn1;
            float ps0 = 0.f, ps1 = 0.f;
#pragma unroll
            for (int nt = 0; nt < 8; nt++) {
                S[nt][0] = ex2f(S[nt][0] - mn0);
                S[nt][1] = ex2f(S[nt][1] - mn0);
                S[nt][2] = ex2f(S[nt][2] - mn1);
                S[nt][3] = ex2f(S[nt][3] - mn1);
                ps0 += S[nt][0] + S[nt][1];
                ps1 += S[nt][2] + S[nt][3];
            }
            lrow0 = lrow0 * a0 + ps0;
            lrow1 = lrow1 * a1 + ps1;
#pragma unroll
            for (int dt = 0; dt < 16; dt++) {
                O[dt][0] *= a0; O[dt][1] *= a0;
                O[dt][2] *= a1; O[dt][3] *= a1;
            }

            const int vr_ = (lane & 7) + ((lane >> 3) & 1) * 8;
            const int vu_ = (lane >> 4);
#pragma unroll
            for (int ks2 = 0; ks2 < 4; ks2++) {
                uint32_t ph[4], pl[4];
                {
                    float p0 = S[2 * ks2][0], p1 = S[2 * ks2][1];
                    float p2 = S[2 * ks2][2], p3 = S[2 * ks2][3];
                    float p4 = S[2 * ks2 + 1][0], p5 = S[2 * ks2 + 1][1];
                    float p6 = S[2 * ks2 + 1][2], p7 = S[2 * ks2 + 1][3];
                    ph[0] = pack_bf16x2(p0, p1);
                    ph[1] = pack_bf16x2(p2, p3);
                    ph[2] = pack_bf16x2(p4, p5);
                    ph[3] = pack_bf16x2(p6, p7);
#define RES(x) ((x) - __bfloat162float(__float2bfloat16(x)))
                    pl[0] = pack_bf16x2(RES(p0), RES(p1));
                    pl[1] = pack_bf16x2(RES(p2), RES(p3));
                    pl[2] = pack_bf16x2(RES(p4), RES(p5));
                    pl[3] = pack_bf16x2(RES(p6), RES(p7));
#undef RES
                }
                int vr = ks2 * 16 + vr_;
#pragma unroll
                for (int dp = 0; dp < 8; dp++) {
                    uint32_t voff = vr * 256 + (((dp * 2 + vu_) ^ (vr & 7)) << 4);
                    uint32_t vh4[4], vl4[4];
                    ldsm_x4_t(vh4, st + 2 * FA_KVMAT + voff);
                    ldsm_x4_t(vl4, st + 3 * FA_KVMAT + voff);
                    mma_bf16(O[2 * dp],     ph, vh4[0], vh4[1]);
                    mma_bf16(O[2 * dp],     pl, vh4[0], vh4[1]);
                    mma_bf16(O[2 * dp],     ph, vl4[0], vl4[1]);
                    mma_bf16(O[2 * dp + 1], ph, vh4[2], vh4[3]);
                    mma_bf16(O[2 * dp + 1], pl, vh4[2], vh4[3]);
                    mma_bf16(O[2 * dp + 1], ph, vl4[2], vl4[3]);
                }
            }
        }
        __syncthreads();
    }

    float l0 = lrow0;
    l0 += __shfl_xor_sync(0xffffffffu, l0, 1);
    l0 += __shfl_xor_sync(0xffffffffu, l0, 2);
    float l1 = lrow1;
    l1 += __shfl_xor_sync(0xffffffffu, l1, 1);
    l1 += __shfl_xor_sync(0xffffffffu, l1, 2);
    const float inv0 = 1.0f / l0, inv1 = 1.0f / l1;

    const int b = bh >> 4, h = bh & 15;
    const int n0r = row_lo + (lane >> 2);
    size_t base0 = ((size_t)(b * SEQ + n0r)) * EMB + h * DHEAD + (lane & 3) * 2;
    size_t base1 = base0 + (size_t)8 * EMB;
#pragma unroll
    for (int dt = 0; dt < 16; dt++) {
        float x0 = O[dt][0] * inv0, x1 = O[dt][1] * inv0;
        float x2 = O[dt][2] * inv1, x3 = O[dt][3] * inv1;
        float h0 = __bfloat162float(__float2bfloat16(x0));
        float h1 = __bfloat162float(__float2bfloat16(x1));
        float h2 = __bfloat162float(__float2bfloat16(x2));
        float h3 = __bfloat162float(__float2bfloat16(x3));
        *(uint32_t*)&Ohi[base0 + dt * 8] = pack_bf16x2(x0, x1);
        *(uint32_t*)&Olo[base0 + dt * 8] = pack_bf16x2(x0 - h0, x1 - h1);
        *(uint32_t*)&Ohi[base1 + dt * 8] = pack_bf16x2(x2, x3);
        *(uint32_t*)&Olo[base1 + dt * 8] = pack_bf16x2(x2 - h2, x3 - h3);
    }
}

// ---------------------------------------------------------------------------
// Launch
// ---------------------------------------------------------------------------
extern "C" void kernel_launch(void* const* d_in, const int* in_sizes, int n_in,
                              void* d_out, int out_size)
{
    const float* x    = (const float*)d_in[0];
    const float* Wqkv = (const float*)d_in[1];
    const float* bqkv = (const float*)d_in[2];
    const float* Wo   = (const float*)d_in[3];
    const float* bo   = (const float*)d_in[4];
    float* out = (float*)d_out;
    (void)in_sizes; (void)n_in; (void)out_size;

    float* qkv;
    __nv_bfloat16 *qhi, *qlo, *khi, *klo, *vhi, *vlo;
    __nv_bfloat16 *xhi, *xlo, *ahi, *alo, *wqhi, *wqlo, *wohi, *wolo;
    cudaGetSymbolAddress((void**)&qkv,  g_qkv);
    cudaGetSymbolAddress((void**)&qhi,  g_qhi);
    cudaGetSymbolAddress((void**)&qlo,  g_qlo);
    cudaGetSymbolAddress((void**)&khi,  g_khi);
    cudaGetSymbolAddress((void**)&klo,  g_klo);
    cudaGetSymbolAddress((void**)&vhi,  g_vhi);
    cudaGetSymbolAddress((void**)&vlo,  g_vlo);
    cudaGetSymbolAddress((void**)&xhi,  g_xhi);
    cudaGetSymbolAddress((void**)&xlo,  g_xlo);
    cudaGetSymbolAddress((void**)&ahi,  g_ahi);
    cudaGetSymbolAddress((void**)&alo,  g_alo);
    cudaGetSymbolAddress((void**)&wqhi, g_wqhi);
    cudaGetSymbolAddress((void**)&wqlo, g_wqlo);
    cudaGetSymbolAddress((void**)&wohi, g_wohi);
    cudaGetSymbolAddress((void**)&wolo, g_wolo);

    cudaFuncSetAttribute(gemm_mma_kernel,
                         cudaFuncAttributeMaxDynamicSharedMemorySize, GEMM_SMEM);
    cudaFuncSetAttribute(flash_mma_kernel,
                         cudaFuncAttributeMaxDynamicSharedMemorySize, FA_SMEM);

    // prep
    rope_table_kernel<<<(SEQ * 64) / 256, 256>>>();
    wtrans_kernel<<<dim3(NQKV / 32, KDIM / 32), 256>>>(Wqkv, wqhi, wqlo, NQKV);
    wtrans_kernel<<<dim3(EMB / 32, KDIM / 32), 256>>>(Wo, wohi, wolo, EMB);
    cvt_hilo_kernel<<<(MTOT * EMB / 4 + 255) / 256, 256>>>(x, xhi, xlo, MTOT * EMB / 4);

    // 1) QKV projection
    gemm_mma_kernel<<<dim3(NQKV / 128, MTOT / 128), 256, GEMM_SMEM>>>(
        xhi, xlo, wqhi, wqlo, bqkv, qkv, NQKV);

    // 2) RoPE + split -> bf16 hi/lo Q,K,V
    rope_split_kernel<<<(MTOT * HEADS * 16) / 256, 256>>>(qkv, qhi, qlo, khi, klo, vhi, vlo);

    // 3) Flash attention -> out-proj A hi/lo directly
    flash_mma_kernel<<<dim3(SEQ / 128, BHT), 256, FA_SMEM>>>(
        qhi, qlo, khi, klo, vhi, vlo, ahi, alo);

    // 4) Output projection
    gemm_mma_kernel<<<dim3(EMB / 128, MTOT / 128), 256, GEMM_SMEM>>>(
        ahi, alo, wohi, wolo, bo, out, EMB);
}